// round 4
// baseline (speedup 1.0000x reference)
#include <cuda_runtime.h>

// Problem constants (StridedSparseAttention: B=4, S=4096, D=512, STRIDE=8)
#define BB 4
#define SS 4096
#define DD 512
#define NK 512          // number of strided keys = S/8
#define KSTRIDE 8

#define SCALE 0.044194173824159216f   // 1/sqrt(512)

// Scratch (device globals — no allocations allowed)
__device__ float g_w[(long)BB * SS * NK];   // unnormalized exp(scores), compact [b][i][c]
__device__ float g_rowsum[BB * SS];

// ---------------------------------------------------------------------------
// Kernel 1: QK GEMM. g_w[b][i][c] = (8c<=i) ? exp(q[b][i]·k[b][8c] * scale) : 0
// Tile: 128(M) x 128(N), k-chunk 32. 256 threads, 8x8 microtile.
// rows: 4*ty + j + 64*hj   keys: tx + 16*jj + 64*he  (conflict-free, pitch 36)
// ---------------------------------------------------------------------------
__global__ __launch_bounds__(256, 2) void qk_kernel(
    const float* __restrict__ q, const float* __restrict__ k)
{
    const int b  = blockIdx.z;
    const int mt = blockIdx.y;
    const int nt = blockIdx.x;
    const int i0 = mt * 128;
    const int c0 = nt * 128;
    if (8 * c0 > i0 + 127) return;     // fully masked tile: never read downstream

    __shared__ float As[128][36];
    __shared__ float Bs[128][36];

    const int tid = threadIdx.x;
    const int tx = tid & 15;
    const int ty = tid >> 4;

    const float* qb = q + ((long)b * SS + i0) * DD;
    const float* kb = k + (long)b * SS * DD;

    float acc[8][8];
#pragma unroll
    for (int r = 0; r < 8; r++)
#pragma unroll
        for (int c = 0; c < 8; c++) acc[r][c] = 0.f;

    for (int kc = 0; kc < DD; kc += 32) {
#pragma unroll
        for (int p = 0; p < 4; p++) {
            int idx = tid + 256 * p;
            int r  = idx >> 3;          // 0..127
            int cq = (idx & 7) * 4;     // 0..28
            *reinterpret_cast<float4*>(&As[r][cq]) =
                *reinterpret_cast<const float4*>(qb + (long)r * DD + kc + cq);
            *reinterpret_cast<float4*>(&Bs[r][cq]) =
                *reinterpret_cast<const float4*>(kb + (long)(KSTRIDE * (c0 + r)) * DD + kc + cq);
        }
        __syncthreads();

#pragma unroll
        for (int kq = 0; kq < 32; kq += 4) {
            float4 b8[8];
#pragma unroll
            for (int he = 0; he < 2; he++)
#pragma unroll
                for (int jj = 0; jj < 4; jj++)
                    b8[he * 4 + jj] =
                        *reinterpret_cast<const float4*>(&Bs[tx + 16 * jj + 64 * he][kq]);
#pragma unroll
            for (int rr = 0; rr < 8; rr++) {
                int row = 4 * ty + (rr & 3) + 64 * (rr >> 2);
                float4 a = *reinterpret_cast<const float4*>(&As[row][kq]);
#pragma unroll
                for (int c = 0; c < 8; c++)
                    acc[rr][c] += a.x * b8[c].x + a.y * b8[c].y +
                                  a.z * b8[c].z + a.w * b8[c].w;
            }
        }
        __syncthreads();
    }

    // epilogue: exp + causal predicate, write unnormalized weights
#pragma unroll
    for (int rr = 0; rr < 8; rr++) {
        int i = i0 + 4 * ty + (rr & 3) + 64 * (rr >> 2);
        float* wrow = g_w + ((long)b * SS + i) * NK;
#pragma unroll
        for (int c = 0; c < 8; c++) {
            int cc = c0 + tx + 16 * (c & 3) + 64 * (c >> 2);
            wrow[cc] = (KSTRIDE * cc <= i) ? __expf(acc[rr][c] * SCALE) : 0.f;
        }
    }
}

// ---------------------------------------------------------------------------
// Kernel 2: fused rowsum + full attn row write + mask write.
// One warp per output row. attn rows (B*S of them): compute rowsum over the
// VALID prefix (predicated, immune to stale g_w), store g_rowsum, then write
// the entire 4096-float row (zeros interleaved with normalized weights) with
// coalesced float4 stores. Rows beyond B*S are mask rows.
// ---------------------------------------------------------------------------
__global__ __launch_bounds__(256) void attn_write_kernel(
    float* __restrict__ attn, float* __restrict__ mask, int write_out)
{
    const int row  = blockIdx.x * 8 + (threadIdx.x >> 5);  // 0 .. B*S + S - 1
    const int lane = threadIdx.x & 31;
    const int NROW = BB * SS;

    if (row < NROW) {
        const int i    = row & (SS - 1);
        const int cmax = i >> 3;                 // largest valid key index
        const float* wr = g_w + (long)row * NK;

        // predicated rowsum over valid prefix
        float s = 0.f;
#pragma unroll
        for (int qd = 0; qd < 4; qd++) {
            int base = 4 * (lane + 32 * qd);
            if (base + 3 <= cmax) {
                float4 v = reinterpret_cast<const float4*>(wr)[lane + 32 * qd];
                s += v.x + v.y + v.z + v.w;
            } else if (base <= cmax) {
                float4 v = reinterpret_cast<const float4*>(wr)[lane + 32 * qd];
                s += v.x;
                if (base + 1 <= cmax) s += v.y;
                if (base + 2 <= cmax) s += v.z;
            }
        }
#pragma unroll
        for (int o = 16; o >= 1; o >>= 1) s += __shfl_xor_sync(0xFFFFFFFFu, s, o);

        if (lane == 0) g_rowsum[row] = s;

        if (write_out) {
            const float inv = 1.0f / s;          // c=0 always valid -> s>0
            float4* arow = reinterpret_cast<float4*>(attn + (long)row * SS);
            const int half = lane >> 1;          // for even lanes: c = half + 16g
            const bool even = (lane & 1) == 0;
#pragma unroll 4
            for (int g = 0; g < 32; g++) {
                int t = lane + 32 * g;           // float4 index within row
                float x = 0.f;
                if (even) {
                    int c = half + 16 * g;       // == t>>1
                    if (c <= cmax) x = wr[c] * inv;
                }
                arow[t] = make_float4(x, 0.f, 0.f, 0.f);
            }
        }
    } else if (write_out) {
        const int i = row - NROW;                // mask row index
        float4* mrow = reinterpret_cast<float4*>(mask + (long)i * SS);
        const int thr = i >> 2;                  // t <= thr && t even -> 1
        const bool even = (lane & 1) == 0;
#pragma unroll 4
        for (int g = 0; g < 32; g++) {
            int t = lane + 32 * g;
            float x = (even && t <= thr) ? 1.0f : 0.f;
            mrow[t] = make_float4(x, 0.f, 0.f, 0.f);
        }
    }
}

// ---------------------------------------------------------------------------
// Kernel 3: PV GEMM. out[b][i][d] = inv_rowsum * sum_c w[b][i][c]*v[b][8c][d]
// Tile: 128(M rows) x 128(N d-cols), key-chunk 32. 8x8 microtile.
// rows: 4*ty + j + 64*hj   d-cols: 4*tx + e + 64*he (float4 acc groups)
// ---------------------------------------------------------------------------
__global__ __launch_bounds__(256, 2) void pv_kernel(
    const float* __restrict__ v, float* __restrict__ out)
{
    const int b  = blockIdx.z;
    const int mt = 31 - blockIdx.y;   // heavy tiles first
    const int nt = blockIdx.x;
    const int i0 = mt * 128;
    const int d0 = nt * 128;

    __shared__ float As[128][36];     // W rows x 32 keys
    __shared__ float Bs[32][132];     // 32 keys x 128 d

    const int tid = threadIdx.x;
    const int tx = tid & 15;
    const int ty = tid >> 4;

    const float* wb = g_w + ((long)b * SS + i0) * NK;
    const float* vb = v + (long)b * SS * DD;

    float4 accf[8][2];
#pragma unroll
    for (int r = 0; r < 8; r++)
#pragma unroll
        for (int h = 0; h < 2; h++) accf[r][h] = make_float4(0.f, 0.f, 0.f, 0.f);

    int nch = ((128 * mt + 127) >> 8) + 1;    // chunks with any valid key
    if (nch > 16) nch = 16;

    for (int ck = 0; ck < nch; ck++) {
        const int key0 = ck * 32;
#pragma unroll
        for (int p = 0; p < 4; p++) {
            int idx = tid + 256 * p;
            {   // As: 128 rows x 32 keys
                int r  = idx >> 3;
                int cq = (idx & 7) * 4;
                *reinterpret_cast<float4*>(&As[r][cq]) =
                    *reinterpret_cast<const float4*>(wb + (long)r * NK + key0 + cq);
            }
            {   // Bs: 32 key rows x 128 d
                int r  = idx >> 5;          // 0..31
                int c4 = (idx & 31) * 4;    // 0..124
                *reinterpret_cast<float4*>(&Bs[r][c4]) =
                    *reinterpret_cast<const float4*>(
                        vb + (long)(KSTRIDE * (key0 + r)) * DD + d0 + c4);
            }
        }
        __syncthreads();

#pragma unroll
        for (int cq = 0; cq < 32; cq += 4) {
            float4 b8[4][2];    // [key-within-quad][he]
#pragma unroll
            for (int cc = 0; cc < 4; cc++)
#pragma unroll
                for (int he = 0; he < 2; he++)
                    b8[cc][he] = *reinterpret_cast<const float4*>(
                        &Bs[cq + cc][4 * tx + 64 * he]);
#pragma unroll
            for (int rr = 0; rr < 8; rr++) {
                int row = 4 * ty + (rr & 3) + 64 * (rr >> 2);
                float4 a = *reinterpret_cast<const float4*>(&As[row][cq]);
#pragma unroll
                for (int he = 0; he < 2; he++) {
                    accf[rr][he].x += a.x * b8[0][he].x + a.y * b8[1][he].x +
                                      a.z * b8[2][he].x + a.w * b8[3][he].x;
                    accf[rr][he].y += a.x * b8[0][he].y + a.y * b8[1][he].y +
                                      a.z * b8[2][he].y + a.w * b8[3][he].y;
                    accf[rr][he].z += a.x * b8[0][he].z + a.y * b8[1][he].z +
                                      a.z * b8[2][he].z + a.w * b8[3][he].z;
                    accf[rr][he].w += a.x * b8[0][he].w + a.y * b8[1][he].w +
                                      a.z * b8[2][he].w + a.w * b8[3][he].w;
                }
            }
        }
        __syncthreads();
    }

    // epilogue: normalize, coalesced float4 stores
#pragma unroll
    for (int rr = 0; rr < 8; rr++) {
        int i = i0 + 4 * ty + (rr & 3) + 64 * (rr >> 2);
        float inv = 1.0f / g_rowsum[b * SS + i];
#pragma unroll
        for (int he = 0; he < 2; he++) {
            float4 o = accf[rr][he];
            o.x *= inv; o.y *= inv; o.z *= inv; o.w *= inv;
            *reinterpret_cast<float4*>(
                out + ((long)b * SS + i) * DD + d0 + 4 * tx + 64 * he) = o;
        }
    }
}

// ---------------------------------------------------------------------------
// Launch
// ---------------------------------------------------------------------------
extern "C" void kernel_launch(void* const* d_in, const int* in_sizes, int n_in,
                              void* d_out, int out_size)
{
    const float* q = (const float*)d_in[0];
    const float* k = (const float*)d_in[1];
    const float* v = (const float*)d_in[2];
    float* out = (float*)d_out;

    const long n_out  = (long)BB * SS * DD;       //  8,388,608
    const long n_attn = (long)BB * SS * SS;       // 67,108,864
    const long n_mask = (long)SS * SS;            // 16,777,216
    const long need = n_out + n_attn + n_mask;

    const int full = ((long)out_size >= need) ? 1 : 0;
    float* attn = out + n_out;
    float* mask = attn + n_attn;

    qk_kernel<<<dim3(4, 32, BB), 256>>>(q, k);

    // one warp per row: B*S attn rows + S mask rows, 8 warps per block
    attn_write_kernel<<<(BB * SS + SS) / 8, 256>>>(attn, mask, full);

    pv_kernel<<<dim3(4, 32, BB), 256>>>(v, out);
}

// round 5
// speedup vs baseline: 1.5208x; 1.5208x over previous
#include <cuda_runtime.h>

// Problem constants (StridedSparseAttention: B=4, S=4096, D=512, STRIDE=8)
#define BB 4
#define SS 4096
#define DD 512
#define NK 512          // number of strided keys = S/8
#define KSTRIDE 8

#define SCALE 0.044194173824159216f   // 1/sqrt(512)

// Scratch (device globals — no allocations allowed)
__device__ float g_w[(long)BB * SS * NK];   // unnormalized exp(scores), compact [b][i][c]
__device__ float g_rowsum[BB * SS];

// ---------------------------------------------------------------------------
// Kernel 1: QK GEMM. g_w[b][i][c] = (8c<=i) ? exp(q[b][i]·k[b][8c]*scale) : 0
// Tile: M=64 queries, N=64 keys, k-chunk=32. 256 threads, 4x4 microtiles.
// (R2-validated shape: regs=64, no spills, LDS conflict-free via pitch 36.)
// ---------------------------------------------------------------------------
__global__ __launch_bounds__(256) void qk_kernel(
    const float* __restrict__ q, const float* __restrict__ k)
{
    const int b  = blockIdx.z;
    const int mt = blockIdx.y;     // query tile
    const int nt = blockIdx.x;     // key tile
    const int i0 = mt * 64;
    const int c0 = nt * 64;
    if (8 * c0 > i0 + 63) return;  // tile fully masked (causal on strided keys)

    __shared__ float As[64][36];   // 32 k-dims + pad (odd quad stride = 9)
    __shared__ float Bs[64][36];

    const int tid = threadIdx.x;
    const int tx = tid & 15;
    const int ty = tid >> 4;

    const float* qb = q + ((long)b * SS + i0) * DD;
    const float* kb = k + (long)b * SS * DD;

    float acc[4][4];
#pragma unroll
    for (int j = 0; j < 4; j++)
#pragma unroll
        for (int jj = 0; jj < 4; jj++) acc[j][jj] = 0.f;

    for (int kc = 0; kc < DD; kc += 32) {
#pragma unroll
        for (int p = 0; p < 2; p++) {
            int idx = tid + 256 * p;
            int r  = idx >> 3;          // 0..63
            int cq = (idx & 7) * 4;     // 0..28
            *reinterpret_cast<float4*>(&As[r][cq]) =
                *reinterpret_cast<const float4*>(qb + (long)r * DD + kc + cq);
            *reinterpret_cast<float4*>(&Bs[r][cq]) =
                *reinterpret_cast<const float4*>(kb + (long)(KSTRIDE * (c0 + r)) * DD + kc + cq);
        }
        __syncthreads();

#pragma unroll
        for (int kq = 0; kq < 32; kq += 4) {
            float a[4][4], bb[4][4];
#pragma unroll
            for (int j = 0; j < 4; j++)
                *reinterpret_cast<float4*>(a[j]) =
                    *reinterpret_cast<const float4*>(&As[4 * ty + j][kq]);
#pragma unroll
            for (int jj = 0; jj < 4; jj++)
                *reinterpret_cast<float4*>(bb[jj]) =
                    *reinterpret_cast<const float4*>(&Bs[tx + 16 * jj][kq]);
#pragma unroll
            for (int j = 0; j < 4; j++)
#pragma unroll
                for (int jj = 0; jj < 4; jj++)
#pragma unroll
                    for (int kk = 0; kk < 4; kk++)
                        acc[j][jj] += a[j][kk] * bb[jj][kk];
        }
        __syncthreads();
    }

    // epilogue: exp + causal predicate, write unnormalized weights
#pragma unroll
    for (int j = 0; j < 4; j++) {
        int i = i0 + 4 * ty + j;
        float* wrow = g_w + ((long)b * SS + i) * NK;
#pragma unroll
        for (int jj = 0; jj < 4; jj++) {
            int c = c0 + tx + 16 * jj;
            wrow[c] = (KSTRIDE * c <= i) ? __expf(acc[j][jj] * SCALE) : 0.f;
        }
    }
}

// ---------------------------------------------------------------------------
// Kernel 2: fused rowsum + full attn row write + mask write (R4-validated).
// One warp per output row. attn rows: predicated rowsum over VALID prefix
// (immune to stale g_w in causally-skipped tiles), store g_rowsum, then one
// fully-coalesced float4 pass writes the whole 4096-float row (zeros +
// normalized weights). Rows beyond B*S are mask rows.
// ---------------------------------------------------------------------------
__global__ __launch_bounds__(256) void attn_write_kernel(
    float* __restrict__ attn, float* __restrict__ mask, int write_out)
{
    const int row  = blockIdx.x * 8 + (threadIdx.x >> 5);  // 0 .. B*S + S - 1
    const int lane = threadIdx.x & 31;
    const int NROW = BB * SS;

    if (row < NROW) {
        const int i    = row & (SS - 1);
        const int cmax = i >> 3;                 // largest valid key index
        const float* wr = g_w + (long)row * NK;

        float s = 0.f;
#pragma unroll
        for (int qd = 0; qd < 4; qd++) {
            int base = 4 * (lane + 32 * qd);
            if (base + 3 <= cmax) {
                float4 v = reinterpret_cast<const float4*>(wr)[lane + 32 * qd];
                s += v.x + v.y + v.z + v.w;
            } else if (base <= cmax) {
                float4 v = reinterpret_cast<const float4*>(wr)[lane + 32 * qd];
                s += v.x;
                if (base + 1 <= cmax) s += v.y;
                if (base + 2 <= cmax) s += v.z;
            }
        }
#pragma unroll
        for (int o = 16; o >= 1; o >>= 1) s += __shfl_xor_sync(0xFFFFFFFFu, s, o);

        if (lane == 0) g_rowsum[row] = s;

        if (write_out) {
            const float inv = 1.0f / s;          // c=0 always valid -> s>0
            float4* arow = reinterpret_cast<float4*>(attn + (long)row * SS);
            const int half = lane >> 1;
            const bool even = (lane & 1) == 0;
#pragma unroll 4
            for (int g = 0; g < 32; g++) {
                int t = lane + 32 * g;           // float4 index within row
                float x = 0.f;
                if (even) {
                    int c = half + 16 * g;       // == t>>1
                    if (c <= cmax) x = wr[c] * inv;
                }
                arow[t] = make_float4(x, 0.f, 0.f, 0.f);
            }
        }
    } else if (write_out) {
        const int i = row - NROW;                // mask row index
        float4* mrow = reinterpret_cast<float4*>(mask + (long)i * SS);
        const int thr = i >> 2;                  // t <= thr && t even -> 1
        const bool even = (lane & 1) == 0;
#pragma unroll 4
        for (int g = 0; g < 32; g++) {
            int t = lane + 32 * g;
            float x = (even && t <= thr) ? 1.0f : 0.f;
            mrow[t] = make_float4(x, 0.f, 0.f, 0.f);
        }
    }
}

// ---------------------------------------------------------------------------
// Kernel 3: PV GEMM. out[b][i][d] = inv_rowsum * sum_c w[b][i][c]*v[b][8c][d]
// Tile: M=64 rows, N=64 d-cols, key-chunk=32. 4x4 microtile (R2-validated).
// Heavy tiles (large mt -> more chunks) scheduled first.
// ---------------------------------------------------------------------------
__global__ __launch_bounds__(256) void pv_kernel(
    const float* __restrict__ v, float* __restrict__ out)
{
    const int b  = blockIdx.z;
    const int mt = 63 - blockIdx.y;   // heavy tiles first
    const int nt = blockIdx.x;
    const int i0 = mt * 64;
    const int d0 = nt * 64;

    __shared__ float As[64][36];   // W rows x 32 keys (+pad)
    __shared__ float Bs[32][68];   // 32 keys x 64 d   (+pad, odd quad stride = 17)

    const int tid = threadIdx.x;
    const int tx = tid & 15;
    const int ty = tid >> 4;

    const float* wb = g_w + ((long)b * SS + i0) * NK;
    const float* vb = v + (long)b * SS * DD;

    float acc[4][4];
#pragma unroll
    for (int j = 0; j < 4; j++)
#pragma unroll
        for (int jj = 0; jj < 4; jj++) acc[j][jj] = 0.f;

    int nch = ((64 * mt + 63) >> 8) + 1;   // chunks with any valid key
    if (nch > 16) nch = 16;

    for (int ck = 0; ck < nch; ck++) {
        const int key0 = ck * 32;
#pragma unroll
        for (int p = 0; p < 2; p++) {
            int idx = tid + 256 * p;
            int r  = idx >> 3;
            int cq = (idx & 7) * 4;
            *reinterpret_cast<float4*>(&As[r][cq]) =
                *reinterpret_cast<const float4*>(wb + (long)r * NK + key0 + cq);
        }
#pragma unroll
        for (int p = 0; p < 2; p++) {
            int idx = tid + 256 * p;
            int r  = idx >> 4;          // 0..31
            int c4 = (idx & 15) * 4;    // 0..60
            *reinterpret_cast<float4*>(&Bs[r][c4]) =
                *reinterpret_cast<const float4*>(
                    vb + (long)(KSTRIDE * (key0 + r)) * DD + d0 + c4);
        }
        __syncthreads();

#pragma unroll
        for (int cq = 0; cq < 32; cq += 4) {
            float a[4][4], bb[4][4];
#pragma unroll
            for (int j = 0; j < 4; j++)
                *reinterpret_cast<float4*>(a[j]) =
                    *reinterpret_cast<const float4*>(&As[4 * ty + j][cq]);
#pragma unroll
            for (int cc = 0; cc < 4; cc++)
                *reinterpret_cast<float4*>(bb[cc]) =
                    *reinterpret_cast<const float4*>(&Bs[cq + cc][4 * tx]);
#pragma unroll
            for (int j = 0; j < 4; j++)
#pragma unroll
                for (int cc = 0; cc < 4; cc++)
#pragma unroll
                    for (int jj = 0; jj < 4; jj++)
                        acc[j][jj] += a[j][cc] * bb[cc][jj];
        }
        __syncthreads();
    }

    // epilogue: normalize by rowsum, coalesced float4 store
#pragma unroll
    for (int j = 0; j < 4; j++) {
        int i = i0 + 4 * ty + j;
        float inv = 1.0f / g_rowsum[b * SS + i];
        float4 o;
        o.x = acc[j][0] * inv;
        o.y = acc[j][1] * inv;
        o.z = acc[j][2] * inv;
        o.w = acc[j][3] * inv;
        *reinterpret_cast<float4*>(out + ((long)b * SS + i) * DD + d0 + 4 * tx) = o;
    }
}

// ---------------------------------------------------------------------------
// Launch
// ---------------------------------------------------------------------------
extern "C" void kernel_launch(void* const* d_in, const int* in_sizes, int n_in,
                              void* d_out, int out_size)
{
    const float* q = (const float*)d_in[0];
    const float* k = (const float*)d_in[1];
    const float* v = (const float*)d_in[2];
    float* out = (float*)d_out;

    const long n_out  = (long)BB * SS * DD;       //  8,388,608
    const long n_attn = (long)BB * SS * SS;       // 67,108,864
    const long n_mask = (long)SS * SS;            // 16,777,216
    const long need = n_out + n_attn + n_mask;

    const int full = ((long)out_size >= need) ? 1 : 0;
    float* attn = out + n_out;
    float* mask = attn + n_attn;

    qk_kernel<<<dim3(NK / 64, SS / 64, BB), 256>>>(q, k);

    // one warp per row: B*S attn rows + S mask rows, 8 warps per block
    attn_write_kernel<<<(BB * SS + SS) / 8, 256>>>(attn, mask, full);

    pv_kernel<<<dim3(DD / 64, SS / 64, BB), 256>>>(v, out);
}

// round 6
// speedup vs baseline: 2.3203x; 1.5256x over previous
#include <cuda_runtime.h>
#include <cuda_bf16.h>

// Problem constants (StridedSparseAttention: B=4, S=4096, D=512, STRIDE=8)
#define BB 4
#define SS 4096
#define DD 512
#define NK 512          // number of strided keys = S/8
#define KSTRIDE 8
#define DP2 256         // DD/2 (b32 pairs per row)
#define NKP2 256        // NK/2

#define SCALE 0.044194173824159216f   // 1/sqrt(512)

// Scratch (device globals — no allocations allowed). uint = packed bf16x2.
__device__ unsigned g_qhi[(long)BB * SS * DP2];
__device__ unsigned g_qlo[(long)BB * SS * DP2];
__device__ unsigned g_khi[BB * NK * DP2];
__device__ unsigned g_klo[BB * NK * DP2];
__device__ unsigned g_vthi[BB * DD * NKP2];   // vT[d][c] hi
__device__ unsigned g_vtlo[BB * DD * NKP2];
__device__ float    g_w  [(long)BB * SS * NK];   // unnormalized exp(scores)
__device__ unsigned g_whi[(long)BB * SS * NKP2]; // normalized w, bf16 hi
__device__ unsigned g_wlo[(long)BB * SS * NKP2];

// ---------------------------------------------------------------------------
// helpers
// ---------------------------------------------------------------------------
__device__ __forceinline__ void split2(float x, float y, unsigned& hi, unsigned& lo) {
    __nv_bfloat16 hx = __float2bfloat16_rn(x);
    __nv_bfloat16 hy = __float2bfloat16_rn(y);
    float rx = x - __bfloat162float(hx);
    float ry = y - __bfloat162float(hy);
    __nv_bfloat162 h2; h2.x = hx; h2.y = hy;
    __nv_bfloat162 l2; l2.x = __float2bfloat16_rn(rx); l2.y = __float2bfloat16_rn(ry);
    hi = *reinterpret_cast<unsigned*>(&h2);
    lo = *reinterpret_cast<unsigned*>(&l2);
}

__device__ __forceinline__ void mma_bf16(float* d, const unsigned* a, const unsigned* b) {
    asm volatile(
        "mma.sync.aligned.m16n8k16.row.col.f32.bf16.bf16.f32 "
        "{%0,%1,%2,%3},{%4,%5,%6,%7},{%8,%9},{%0,%1,%2,%3};\n"
        : "+f"(d[0]), "+f"(d[1]), "+f"(d[2]), "+f"(d[3])
        : "r"(a[0]), "r"(a[1]), "r"(a[2]), "r"(a[3]), "r"(b[0]), "r"(b[1]));
}

// ---------------------------------------------------------------------------
// Prep A: q -> hi/lo (same layout); strided k -> khi/klo [b][c][d]
// ---------------------------------------------------------------------------
__global__ __launch_bounds__(256) void prep_qk_kernel(
    const float* __restrict__ q, const float* __restrict__ k)
{
    const long NQ  = (long)BB * SS * DP2;     // uints of q
    const long NKU = (long)BB * NK * DP2;     // uints of strided k
    long t0 = (long)blockIdx.x * blockDim.x + threadIdx.x;
    long str = (long)gridDim.x * blockDim.x;

    for (long t = t0; t < NQ; t += str) {
        float2 f = reinterpret_cast<const float2*>(q)[t];
        unsigned hi, lo; split2(f.x, f.y, hi, lo);
        g_qhi[t] = hi; g_qlo[t] = lo;
    }
    for (long t = t0; t < NKU; t += str) {
        int b  = (int)(t / (NK * DP2));
        int r  = (int)((t / DP2) % NK);
        int dq = (int)(t % DP2);
        float2 f = reinterpret_cast<const float2*>(k)[((long)b * SS + KSTRIDE * r) * DP2 + dq];
        unsigned hi, lo; split2(f.x, f.y, hi, lo);
        g_khi[t] = hi; g_klo[t] = lo;
    }
}

// ---------------------------------------------------------------------------
// Prep B: strided v -> transposed vT[d][c] hi/lo. 32x32 smem transpose tiles.
// grid (ct=16, dt=16, b=4), 256 threads.
// ---------------------------------------------------------------------------
__global__ __launch_bounds__(256) void transpose_v_kernel(const float* __restrict__ v)
{
    __shared__ float sm[32][33];
    const int b  = blockIdx.z;
    const int c0 = blockIdx.x * 32;
    const int d0 = blockIdx.y * 32;
    const int tid = threadIdx.x;
    const int r = tid >> 3;      // 0..31
    const int j = tid & 7;       // 0..7

    float4 f = *reinterpret_cast<const float4*>(
        v + ((long)b * SS + KSTRIDE * (c0 + r)) * DD + d0 + 4 * j);
    sm[r][4 * j + 0] = f.x; sm[r][4 * j + 1] = f.y;
    sm[r][4 * j + 2] = f.z; sm[r][4 * j + 3] = f.w;
    __syncthreads();

    // thread writes d-row r, c = c0 + 4j .. 4j+3
    float v0 = sm[4 * j + 0][r], v1 = sm[4 * j + 1][r];
    float v2 = sm[4 * j + 2][r], v3 = sm[4 * j + 3][r];
    unsigned h0, l0, h1, l1;
    split2(v0, v1, h0, l0);
    split2(v2, v3, h1, l1);
    long base = ((long)b * DD + d0 + r) * NKP2 + (c0 >> 1) + 2 * j;
    g_vthi[base] = h0; g_vthi[base + 1] = h1;
    g_vtlo[base] = l0; g_vtlo[base + 1] = l1;
}

// ---------------------------------------------------------------------------
// QK GEMM via split-bf16 mma.m16n8k16.
// CTA tile 128(i) x 64(c), 8 warps (4 M x 2 N), warp tile 32x32, kc=32.
// g_w[b][i][c] = (8c<=i) ? exp(score*scale) : 0
// ---------------------------------------------------------------------------
__global__ __launch_bounds__(256) void qk_mma_kernel()
{
    const int b  = blockIdx.z;
    const int mt = blockIdx.y;
    const int nt = blockIdx.x;
    const int i0 = mt * 128;
    const int c0 = nt * 64;
    if (8 * c0 > i0 + 127) return;   // fully masked tile

    __shared__ unsigned sAh[128 * 20], sAl[128 * 20];
    __shared__ unsigned sBh[64 * 20],  sBl[64 * 20];

    const int tid  = threadIdx.x;
    const int lane = tid & 31;
    const int wid  = tid >> 5;
    const int wm   = wid & 3;     // 0..3 -> 32-row slices
    const int wn   = wid >> 2;    // 0..1 -> 32-key slices
    const int g    = lane >> 2;
    const int tq   = lane & 3;

    const unsigned* qh = g_qhi + ((long)b * SS + i0) * DP2;
    const unsigned* ql = g_qlo + ((long)b * SS + i0) * DP2;
    const unsigned* kh = g_khi + ((long)b * NK + c0) * DP2;
    const unsigned* kl = g_klo + ((long)b * NK + c0) * DP2;

    float acc[2][4][4];
#pragma unroll
    for (int m = 0; m < 2; m++)
#pragma unroll
        for (int n = 0; n < 4; n++)
#pragma unroll
            for (int e = 0; e < 4; e++) acc[m][n][e] = 0.f;

    for (int ch = 0; ch < 16; ch++) {
        const int kb32 = ch * 16;
        // A tiles: 128 rows x 16 b32  (hi + lo)
#pragma unroll
        for (int p = 0; p < 2; p++) {
            int ii = tid + 256 * p;
            int r  = ii >> 2;
            int q4 = (ii & 3) * 4;
            *reinterpret_cast<uint4*>(&sAh[r * 20 + q4]) =
                *reinterpret_cast<const uint4*>(qh + (long)r * DP2 + kb32 + q4);
            *reinterpret_cast<uint4*>(&sAl[r * 20 + q4]) =
                *reinterpret_cast<const uint4*>(ql + (long)r * DP2 + kb32 + q4);
        }
        // B tiles: 64 rows x 16 b32
        {
            int r  = tid >> 2;
            int q4 = (tid & 3) * 4;
            *reinterpret_cast<uint4*>(&sBh[r * 20 + q4]) =
                *reinterpret_cast<const uint4*>(kh + (long)r * DP2 + kb32 + q4);
            *reinterpret_cast<uint4*>(&sBl[r * 20 + q4]) =
                *reinterpret_cast<const uint4*>(kl + (long)r * DP2 + kb32 + q4);
        }
        __syncthreads();

#pragma unroll
        for (int ks = 0; ks < 2; ks++) {
            const int kb = ks * 8;
            unsigned Ah[2][4], Al[2][4], Bh[4][2], Bl[4][2];
#pragma unroll
            for (int m = 0; m < 2; m++) {
                int r = wm * 32 + m * 16 + g;
                Ah[m][0] = sAh[r * 20 + kb + tq];
                Ah[m][1] = sAh[(r + 8) * 20 + kb + tq];
                Ah[m][2] = sAh[r * 20 + kb + 4 + tq];
                Ah[m][3] = sAh[(r + 8) * 20 + kb + 4 + tq];
                Al[m][0] = sAl[r * 20 + kb + tq];
                Al[m][1] = sAl[(r + 8) * 20 + kb + tq];
                Al[m][2] = sAl[r * 20 + kb + 4 + tq];
                Al[m][3] = sAl[(r + 8) * 20 + kb + 4 + tq];
            }
#pragma unroll
            for (int n = 0; n < 4; n++) {
                int c = wn * 32 + n * 8 + g;
                Bh[n][0] = sBh[c * 20 + kb + tq];
                Bh[n][1] = sBh[c * 20 + kb + 4 + tq];
                Bl[n][0] = sBl[c * 20 + kb + tq];
                Bl[n][1] = sBl[c * 20 + kb + 4 + tq];
            }
#pragma unroll
            for (int m = 0; m < 2; m++)
#pragma unroll
                for (int n = 0; n < 4; n++) {
                    mma_bf16(acc[m][n], Ah[m], Bh[n]);
                    mma_bf16(acc[m][n], Ah[m], Bl[n]);
                    mma_bf16(acc[m][n], Al[m], Bh[n]);
                }
        }
        __syncthreads();
    }

    // epilogue: exp + causal predicate -> g_w
#pragma unroll
    for (int m = 0; m < 2; m++)
#pragma unroll
        for (int n = 0; n < 4; n++) {
            int ia = i0 + wm * 32 + m * 16 + g;
            int ca = c0 + wn * 32 + n * 8 + 2 * tq;
            float* w0 = g_w + ((long)b * SS + ia) * NK + ca;
            float2 o;
            o.x = (KSTRIDE * ca <= ia)       ? __expf(acc[m][n][0] * SCALE) : 0.f;
            o.y = (KSTRIDE * (ca + 1) <= ia) ? __expf(acc[m][n][1] * SCALE) : 0.f;
            *reinterpret_cast<float2*>(w0) = o;
            int ib = ia + 8;
            float* w1 = g_w + ((long)b * SS + ib) * NK + ca;
            float2 p;
            p.x = (KSTRIDE * ca <= ib)       ? __expf(acc[m][n][2] * SCALE) : 0.f;
            p.y = (KSTRIDE * (ca + 1) <= ib) ? __expf(acc[m][n][3] * SCALE) : 0.f;
            *reinterpret_cast<float2*>(w1) = p;
        }
}

// ---------------------------------------------------------------------------
// Fused rowsum + normalized-w bf16 split + full attn row write + mask write.
// One warp per row. whi/wlo ALWAYS written (zeros beyond cmax) — PV input.
// ---------------------------------------------------------------------------
__global__ __launch_bounds__(256) void attn_write_kernel(
    float* __restrict__ attn, float* __restrict__ mask, int write_out)
{
    const int row  = blockIdx.x * 8 + (threadIdx.x >> 5);  // 0 .. B*S + S - 1
    const int lane = threadIdx.x & 31;
    const int NROW = BB * SS;

    if (row < NROW) {
        const int i    = row & (SS - 1);
        const int cmax = i >> 3;
        const float* wr = g_w + (long)row * NK;

        float4 vq[4];
        float s = 0.f;
#pragma unroll
        for (int qd = 0; qd < 4; qd++) {
            int base = 4 * (lane + 32 * qd);
            if (base <= cmax) {
                vq[qd] = reinterpret_cast<const float4*>(wr)[lane + 32 * qd];
                s += vq[qd].x;
                if (base + 1 <= cmax) s += vq[qd].y;
                if (base + 2 <= cmax) s += vq[qd].z;
                if (base + 3 <= cmax) s += vq[qd].w;
            } else {
                vq[qd] = make_float4(0.f, 0.f, 0.f, 0.f);
            }
        }
#pragma unroll
        for (int o = 16; o >= 1; o >>= 1) s += __shfl_xor_sync(0xFFFFFFFFu, s, o);

        const float inv = 1.0f / s;              // c=0 always valid -> s>0

        // normalized w -> bf16 hi/lo (zeros beyond cmax), coalesced uint2
#pragma unroll
        for (int qd = 0; qd < 4; qd++) {
            int base = 4 * (lane + 32 * qd);
            float w0 = (base     <= cmax) ? vq[qd].x * inv : 0.f;
            float w1 = (base + 1 <= cmax) ? vq[qd].y * inv : 0.f;
            float w2 = (base + 2 <= cmax) ? vq[qd].z * inv : 0.f;
            float w3 = (base + 3 <= cmax) ? vq[qd].w * inv : 0.f;
            unsigned h0, l0, h1, l1;
            split2(w0, w1, h0, l0);
            split2(w2, w3, h1, l1);
            long u = (long)row * NKP2 + 2 * (lane + 32 * qd);
            *reinterpret_cast<uint2*>(&g_whi[u]) = make_uint2(h0, h1);
            *reinterpret_cast<uint2*>(&g_wlo[u]) = make_uint2(l0, l1);
        }

        if (write_out) {
            float4* arow = reinterpret_cast<float4*>(attn + (long)row * SS);
            const int half = lane >> 1;
            const bool even = (lane & 1) == 0;
#pragma unroll 4
            for (int gg = 0; gg < 32; gg++) {
                int t = lane + 32 * gg;          // float4 index within row
                float x = 0.f;
                if (even) {
                    int c = half + 16 * gg;      // == t>>1
                    if (c <= cmax) x = wr[c] * inv;
                }
                arow[t] = make_float4(x, 0.f, 0.f, 0.f);
            }
        }
    } else if (write_out) {
        const int i = row - NROW;                // mask row index
        float4* mrow = reinterpret_cast<float4*>(mask + (long)i * SS);
        const int thr = i >> 2;
        const bool even = (lane & 1) == 0;
#pragma unroll 4
        for (int gg = 0; gg < 32; gg++) {
            int t = lane + 32 * gg;
            float x = (even && t <= thr) ? 1.0f : 0.f;
            mrow[t] = make_float4(x, 0.f, 0.f, 0.f);
        }
    }
}

// ---------------------------------------------------------------------------
// PV GEMM via split-bf16 mma: out[b][i][d] = sum_c wn[i][c] * v[8c][d]
// A = g_whi/g_wlo [i][c], B = g_vthi/g_vtlo [d][c]. CTA 128(i) x 64(d).
// w is pre-normalized -> no rowsum epilogue. Causal chunk skip, heavy first.
// ---------------------------------------------------------------------------
__global__ __launch_bounds__(256) void pv_mma_kernel(float* __restrict__ out)
{
    const int b  = blockIdx.z;
    const int mt = 31 - blockIdx.y;   // heavy tiles first
    const int nt = blockIdx.x;
    const int i0 = mt * 128;
    const int d0 = nt * 64;

    __shared__ unsigned sAh[128 * 20], sAl[128 * 20];
    __shared__ unsigned sBh[64 * 20],  sBl[64 * 20];

    const int tid  = threadIdx.x;
    const int lane = tid & 31;
    const int wid  = tid >> 5;
    const int wm   = wid & 3;
    const int wn   = wid >> 2;
    const int g    = lane >> 2;
    const int tq   = lane & 3;

    const unsigned* wh = g_whi + ((long)b * SS + i0) * NKP2;
    const unsigned* wl = g_wlo + ((long)b * SS + i0) * NKP2;
    const unsigned* vh = g_vthi + ((long)b * DD + d0) * NKP2;
    const unsigned* vl = g_vtlo + ((long)b * DD + d0) * NKP2;

    float acc[2][4][4];
#pragma unroll
    for (int m = 0; m < 2; m++)
#pragma unroll
        for (int n = 0; n < 4; n++)
#pragma unroll
            for (int e = 0; e < 4; e++) acc[m][n][e] = 0.f;

    int nch = ((128 * mt + 127) >> 8) + 1;
    if (nch > 16) nch = 16;

    for (int ch = 0; ch < nch; ch++) {
        const int kb32 = ch * 16;
#pragma unroll
        for (int p = 0; p < 2; p++) {
            int ii = tid + 256 * p;
            int r  = ii >> 2;
            int q4 = (ii & 3) * 4;
            *reinterpret_cast<uint4*>(&sAh[r * 20 + q4]) =
                *reinterpret_cast<const uint4*>(wh + (long)r * NKP2 + kb32 + q4);
            *reinterpret_cast<uint4*>(&sAl[r * 20 + q4]) =
                *reinterpret_cast<const uint4*>(wl + (long)r * NKP2 + kb32 + q4);
        }
        {
            int r  = tid >> 2;
            int q4 = (tid & 3) * 4;
            *reinterpret_cast<uint4*>(&sBh[r * 20 + q4]) =
                *reinterpret_cast<const uint4*>(vh + (long)r * NKP2 + kb32 + q4);
            *reinterpret_cast<uint4*>(&sBl[r * 20 + q4]) =
                *reinterpret_cast<const uint4*>(vl + (long)r * NKP2 + kb32 + q4);
        }
        __syncthreads();

#pragma unroll
        for (int ks = 0; ks < 2; ks++) {
            const int kb = ks * 8;
            unsigned Ah[2][4], Al[2][4], Bh[4][2], Bl[4][2];
#pragma unroll
            for (int m = 0; m < 2; m++) {
                int r = wm * 32 + m * 16 + g;
                Ah[m][0] = sAh[r * 20 + kb + tq];
                Ah[m][1] = sAh[(r + 8) * 20 + kb + tq];
                Ah[m][2] = sAh[r * 20 + kb + 4 + tq];
                Ah[m][3] = sAh[(r + 8) * 20 + kb + 4 + tq];
                Al[m][0] = sAl[r * 20 + kb + tq];
                Al[m][1] = sAl[(r + 8) * 20 + kb + tq];
                Al[m][2] = sAl[r * 20 + kb + 4 + tq];
                Al[m][3] = sAl[(r + 8) * 20 + kb + 4 + tq];
            }
#pragma unroll
            for (int n = 0; n < 4; n++) {
                int c = wn * 32 + n * 8 + g;
                Bh[n][0] = sBh[c * 20 + kb + tq];
                Bh[n][1] = sBh[c * 20 + kb + 4 + tq];
                Bl[n][0] = sBl[c * 20 + kb + tq];
                Bl[n][1] = sBl[c * 20 + kb + 4 + tq];
            }
#pragma unroll
            for (int m = 0; m < 2; m++)
#pragma unroll
                for (int n = 0; n < 4; n++) {
                    mma_bf16(acc[m][n], Ah[m], Bh[n]);
                    mma_bf16(acc[m][n], Ah[m], Bl[n]);
                    mma_bf16(acc[m][n], Al[m], Bh[n]);
                }
        }
        __syncthreads();
    }

    // epilogue: direct float2 stores (w pre-normalized)
#pragma unroll
    for (int m = 0; m < 2; m++)
#pragma unroll
        for (int n = 0; n < 4; n++) {
            int ia = i0 + wm * 32 + m * 16 + g;
            int da = d0 + wn * 32 + n * 8 + 2 * tq;
            *reinterpret_cast<float2*>(out + ((long)b * SS + ia) * DD + da) =
                make_float2(acc[m][n][0], acc[m][n][1]);
            *reinterpret_cast<float2*>(out + ((long)b * SS + ia + 8) * DD + da) =
                make_float2(acc[m][n][2], acc[m][n][3]);
        }
}

// ---------------------------------------------------------------------------
// Launch
// ---------------------------------------------------------------------------
extern "C" void kernel_launch(void* const* d_in, const int* in_sizes, int n_in,
                              void* d_out, int out_size)
{
    const float* q = (const float*)d_in[0];
    const float* k = (const float*)d_in[1];
    const float* v = (const float*)d_in[2];
    float* out = (float*)d_out;

    const long n_out  = (long)BB * SS * DD;       //  8,388,608
    const long n_attn = (long)BB * SS * SS;       // 67,108,864
    const long n_mask = (long)SS * SS;            // 16,777,216
    const long need = n_out + n_attn + n_mask;

    const int full = ((long)out_size >= need) ? 1 : 0;
    float* attn = out + n_out;
    float* mask = attn + n_attn;

    prep_qk_kernel<<<4096, 256>>>(q, k);
    transpose_v_kernel<<<dim3(16, 16, BB), 256>>>(v);

    qk_mma_kernel<<<dim3(NK / 64, SS / 128, BB), 256>>>();

    attn_write_kernel<<<(BB * SS + SS) / 8, 256>>>(attn, mask, full);

    pv_mma_kernel<<<dim3(DD / 64, SS / 128, BB), 256>>>(out);
}

// round 8
// speedup vs baseline: 2.3748x; 1.0235x over previous
#include <cuda_runtime.h>
#include <cuda_bf16.h>

// Problem constants (StridedSparseAttention: B=4, S=4096, D=512, STRIDE=8)
#define BB 4
#define SS 4096
#define DD 512
#define NK 512          // number of strided keys = S/8
#define KSTRIDE 8
#define DP2 256         // DD/2 (b32 pairs per row)
#define NKP2 256        // NK/2
#define PITCH 12        // smem row pitch in uints for 8-uint rows (conflict-free)

#define SCALE 0.044194173824159216f   // 1/sqrt(512)

// Scratch (device globals — no allocations allowed). uint = packed bf16x2.
__device__ unsigned g_qhi[(long)BB * SS * DP2];
__device__ unsigned g_qlo[(long)BB * SS * DP2];
__device__ unsigned g_khi[BB * NK * DP2];
__device__ unsigned g_klo[BB * NK * DP2];
__device__ unsigned g_vthi[BB * DD * NKP2];      // vT[d][c] hi
__device__ unsigned g_vtlo[BB * DD * NKP2];
__device__ unsigned g_whi[(long)BB * SS * NKP2]; // UNnormalized exp(score), bf16 hi
__device__ unsigned g_wlo[(long)BB * SS * NKP2];
__device__ float    g_rowsum[BB * SS];

// ---------------------------------------------------------------------------
// helpers
// ---------------------------------------------------------------------------
__device__ __forceinline__ void split2(float x, float y, unsigned& hi, unsigned& lo) {
    __nv_bfloat16 hx = __float2bfloat16_rn(x);
    __nv_bfloat16 hy = __float2bfloat16_rn(y);
    float rx = x - __bfloat162float(hx);
    float ry = y - __bfloat162float(hy);
    __nv_bfloat162 h2; h2.x = hx; h2.y = hy;
    __nv_bfloat162 l2; l2.x = __float2bfloat16_rn(rx); l2.y = __float2bfloat16_rn(ry);
    hi = *reinterpret_cast<unsigned*>(&h2);
    lo = *reinterpret_cast<unsigned*>(&l2);
}

__device__ __forceinline__ void mma_bf16(float* d, const unsigned* a, const unsigned* b) {
    asm volatile(
        "mma.sync.aligned.m16n8k16.row.col.f32.bf16.bf16.f32 "
        "{%0,%1,%2,%3},{%4,%5,%6,%7},{%8,%9},{%0,%1,%2,%3};\n"
        : "+f"(d[0]), "+f"(d[1]), "+f"(d[2]), "+f"(d[3])
        : "r"(a[0]), "r"(a[1]), "r"(a[2]), "r"(a[3]), "r"(b[0]), "r"(b[1]));
}

__device__ __forceinline__ void cp16(unsigned* smem, const unsigned* gmem) {
    unsigned s = (unsigned)__cvta_generic_to_shared(smem);
    asm volatile("cp.async.cg.shared.global [%0], [%1], 16;\n" :: "r"(s), "l"(gmem));
}
#define CP_COMMIT() asm volatile("cp.async.commit_group;\n")
#define CP_WAIT1()  asm volatile("cp.async.wait_group 1;\n")
#define CP_WAIT0()  asm volatile("cp.async.wait_group 0;\n")

// ---------------------------------------------------------------------------
// Prep A: q -> hi/lo (same layout); strided k -> khi/klo [b][c][d]
// ---------------------------------------------------------------------------
__global__ __launch_bounds__(256) void prep_qk_kernel(
    const float* __restrict__ q, const float* __restrict__ k)
{
    const long NQ  = (long)BB * SS * DP2;
    const long NKU = (long)BB * NK * DP2;
    long t0 = (long)blockIdx.x * blockDim.x + threadIdx.x;
    long str = (long)gridDim.x * blockDim.x;

    for (long t = t0; t < NQ; t += str) {
        float2 f = reinterpret_cast<const float2*>(q)[t];
        unsigned hi, lo; split2(f.x, f.y, hi, lo);
        g_qhi[t] = hi; g_qlo[t] = lo;
    }
    for (long t = t0; t < NKU; t += str) {
        int b  = (int)(t / (NK * DP2));
        int r  = (int)((t / DP2) % NK);
        int dq = (int)(t % DP2);
        float2 f = reinterpret_cast<const float2*>(k)[((long)b * SS + KSTRIDE * r) * DP2 + dq];
        unsigned hi, lo; split2(f.x, f.y, hi, lo);
        g_khi[t] = hi; g_klo[t] = lo;
    }
}

// ---------------------------------------------------------------------------
// Prep B: strided v -> transposed vT[d][c] hi/lo. 32x32 smem transpose tiles.
// ---------------------------------------------------------------------------
__global__ __launch_bounds__(256) void transpose_v_kernel(const float* __restrict__ v)
{
    __shared__ float sm[32][33];
    const int b  = blockIdx.z;
    const int c0 = blockIdx.x * 32;
    const int d0 = blockIdx.y * 32;
    const int tid = threadIdx.x;
    const int r = tid >> 3;      // 0..31
    const int j = tid & 7;       // 0..7

    float4 f = *reinterpret_cast<const float4*>(
        v + ((long)b * SS + KSTRIDE * (c0 + r)) * DD + d0 + 4 * j);
    sm[r][4 * j + 0] = f.x; sm[r][4 * j + 1] = f.y;
    sm[r][4 * j + 2] = f.z; sm[r][4 * j + 3] = f.w;
    __syncthreads();

    float v0 = sm[4 * j + 0][r], v1 = sm[4 * j + 1][r];
    float v2 = sm[4 * j + 2][r], v3 = sm[4 * j + 3][r];
    unsigned h0, l0, h1, l1;
    split2(v0, v1, h0, l0);
    split2(v2, v3, h1, l1);
    long base = ((long)b * DD + d0 + r) * NKP2 + (c0 >> 1) + 2 * j;
    g_vthi[base] = h0; g_vthi[base + 1] = h1;
    g_vtlo[base] = l0; g_vtlo[base + 1] = l1;
}

// ---------------------------------------------------------------------------
// QK GEMM, split-bf16 mma, 2-stage cp.async pipeline, k16 chunks.
// CTA 128(i) x 64(c), 8 warps (4M x 2N), warp tile 32x32.
// Epilogue writes UNnormalized whi/wlo (causal-zeroed).
// ---------------------------------------------------------------------------
__global__ __launch_bounds__(256) void qk_mma_kernel()
{
    const int b  = blockIdx.z;
    const int mt = blockIdx.y;
    const int nt = blockIdx.x;
    const int i0 = mt * 128;
    const int c0 = nt * 64;
    if (8 * c0 > i0 + 127) return;   // fully masked tile

    __shared__ unsigned sA[2][2][128 * PITCH];   // [stage][hi/lo]
    __shared__ unsigned sB[2][2][64 * PITCH];

    const int tid  = threadIdx.x;
    const int lane = tid & 31;
    const int wid  = tid >> 5;
    const int wm   = wid & 3;
    const int wn   = wid >> 2;
    const int g    = lane >> 2;
    const int tq   = lane & 3;

    const unsigned* qh = g_qhi + ((long)b * SS + i0) * DP2;
    const unsigned* ql = g_qlo + ((long)b * SS + i0) * DP2;
    const unsigned* kh = g_khi + ((long)b * NK + c0) * DP2;
    const unsigned* kl = g_klo + ((long)b * NK + c0) * DP2;

    const int lr = tid >> 1;          // 0..127
    const int lc = (tid & 1) * 4;     // 0 or 4

    float acc[2][4][4];
#pragma unroll
    for (int m = 0; m < 2; m++)
#pragma unroll
        for (int n = 0; n < 4; n++)
#pragma unroll
            for (int e = 0; e < 4; e++) acc[m][n][e] = 0.f;

#define QK_LOAD(ch, st)                                                          \
    do {                                                                         \
        int kb = (ch) * 8;                                                       \
        cp16(&sA[st][0][lr * PITCH + lc], qh + (long)lr * DP2 + kb + lc);        \
        cp16(&sA[st][1][lr * PITCH + lc], ql + (long)lr * DP2 + kb + lc);        \
        if (tid < 128) {                                                         \
            cp16(&sB[st][0][lr * PITCH + lc], kh + (long)lr * DP2 + kb + lc);    \
            cp16(&sB[st][1][lr * PITCH + lc], kl + (long)lr * DP2 + kb + lc);    \
        }                                                                        \
    } while (0)

    QK_LOAD(0, 0); CP_COMMIT();

    for (int ch = 0; ch < 32; ch++) {
        const int st = ch & 1;
        if (ch + 1 < 32) { QK_LOAD(ch + 1, st ^ 1); CP_COMMIT(); CP_WAIT1(); }
        else             { CP_WAIT0(); }
        __syncthreads();

        unsigned Ah[2][4], Al[2][4], Bh[4][2], Bl[4][2];
#pragma unroll
        for (int m = 0; m < 2; m++) {
            int r = wm * 32 + m * 16 + g;
            Ah[m][0] = sA[st][0][r * PITCH + tq];
            Ah[m][1] = sA[st][0][(r + 8) * PITCH + tq];
            Ah[m][2] = sA[st][0][r * PITCH + 4 + tq];
            Ah[m][3] = sA[st][0][(r + 8) * PITCH + 4 + tq];
            Al[m][0] = sA[st][1][r * PITCH + tq];
            Al[m][1] = sA[st][1][(r + 8) * PITCH + tq];
            Al[m][2] = sA[st][1][r * PITCH + 4 + tq];
            Al[m][3] = sA[st][1][(r + 8) * PITCH + 4 + tq];
        }
#pragma unroll
        for (int n = 0; n < 4; n++) {
            int c = wn * 32 + n * 8 + g;
            Bh[n][0] = sB[st][0][c * PITCH + tq];
            Bh[n][1] = sB[st][0][c * PITCH + 4 + tq];
            Bl[n][0] = sB[st][1][c * PITCH + tq];
            Bl[n][1] = sB[st][1][c * PITCH + 4 + tq];
        }
#pragma unroll
        for (int m = 0; m < 2; m++)
#pragma unroll
            for (int n = 0; n < 4; n++) {
                mma_bf16(acc[m][n], Ah[m], Bh[n]);
                mma_bf16(acc[m][n], Ah[m], Bl[n]);
                mma_bf16(acc[m][n], Al[m], Bh[n]);
            }
        __syncthreads();
    }
#undef QK_LOAD

    // epilogue: exp + causal predicate -> bf16 hi/lo (unnormalized)
#pragma unroll
    for (int m = 0; m < 2; m++)
#pragma unroll
        for (int n = 0; n < 4; n++) {
            int ia = i0 + wm * 32 + m * 16 + g;
            int ca = c0 + wn * 32 + n * 8 + 2 * tq;
            float w0 = (KSTRIDE * ca <= ia)       ? __expf(acc[m][n][0] * SCALE) : 0.f;
            float w1 = (KSTRIDE * (ca + 1) <= ia) ? __expf(acc[m][n][1] * SCALE) : 0.f;
            unsigned hi, lo; split2(w0, w1, hi, lo);
            long u0 = ((long)b * SS + ia) * NKP2 + (ca >> 1);
            g_whi[u0] = hi; g_wlo[u0] = lo;
            int ib = ia + 8;
            float w2 = (KSTRIDE * ca <= ib)       ? __expf(acc[m][n][2] * SCALE) : 0.f;
            float w3 = (KSTRIDE * (ca + 1) <= ib) ? __expf(acc[m][n][3] * SCALE) : 0.f;
            split2(w2, w3, hi, lo);
            long u1 = ((long)b * SS + ib) * NKP2 + (ca >> 1);
            g_whi[u1] = hi; g_wlo[u1] = lo;
        }
}

// ---------------------------------------------------------------------------
// Fused rowsum + full attn row write + mask write. One warp per row.
// Reads whi/wlo, reconstructs w, predicated rowsum -> g_rowsum (for PV),
// stages the compact w row in smem, streams the full 4096-float attn row.
// ---------------------------------------------------------------------------
__global__ __launch_bounds__(256) void attn_write_kernel(
    float* __restrict__ attn, float* __restrict__ mask, int write_out)
{
    __shared__ float sw[8][512];
    const int wp   = threadIdx.x >> 5;
    const int row  = blockIdx.x * 8 + wp;        // 0 .. B*S + S - 1
    const int lane = threadIdx.x & 31;
    const int NROW = BB * SS;

    if (row < NROW) {
        const int i    = row & (SS - 1);
        const int cmax = i >> 3;

        float s = 0.f;
#pragma unroll
        for (int qd = 0; qd < 4; qd++) {
            int u = lane + 32 * qd;              // uint2 index: values 4u..4u+3
            int base = 4 * u;
            uint2 H = *reinterpret_cast<const uint2*>(&g_whi[(long)row * NKP2 + 2 * u]);
            uint2 L = *reinterpret_cast<const uint2*>(&g_wlo[(long)row * NKP2 + 2 * u]);
            float2 h0 = __bfloat1622float2(*reinterpret_cast<__nv_bfloat162*>(&H.x));
            float2 h1 = __bfloat1622float2(*reinterpret_cast<__nv_bfloat162*>(&H.y));
            float2 l0 = __bfloat1622float2(*reinterpret_cast<__nv_bfloat162*>(&L.x));
            float2 l1 = __bfloat1622float2(*reinterpret_cast<__nv_bfloat162*>(&L.y));
            float w0 = (base     <= cmax) ? h0.x + l0.x : 0.f;
            float w1 = (base + 1 <= cmax) ? h0.y + l0.y : 0.f;
            float w2 = (base + 2 <= cmax) ? h1.x + l1.x : 0.f;
            float w3 = (base + 3 <= cmax) ? h1.y + l1.y : 0.f;
            s += (w0 + w1) + (w2 + w3);
            *reinterpret_cast<float4*>(&sw[wp][base]) = make_float4(w0, w1, w2, w3);
        }
#pragma unroll
        for (int o = 16; o >= 1; o >>= 1) s += __shfl_xor_sync(0xFFFFFFFFu, s, o);

        if (lane == 0) g_rowsum[row] = s;
        __syncwarp();

        if (write_out) {
            const float inv = 1.0f / s;          // c=0 always valid -> s>0
            float4* arow = reinterpret_cast<float4*>(attn + (long)row * SS);
            const int half = lane >> 1;
            const bool even = (lane & 1) == 0;
#pragma unroll 4
            for (int gg = 0; gg < 32; gg++) {
                int t = lane + 32 * gg;          // float4 index within row
                float x = 0.f;
                if (even) x = sw[wp][half + 16 * gg] * inv;   // zeros beyond cmax already
                arow[t] = make_float4(x, 0.f, 0.f, 0.f);
            }
        }
    } else if (write_out) {
        const int i = row - NROW;                // mask row index
        float4* mrow = reinterpret_cast<float4*>(mask + (long)i * SS);
        const int thr = i >> 2;
        const bool even = (lane & 1) == 0;
#pragma unroll 4
        for (int gg = 0; gg < 32; gg++) {
            int t = lane + 32 * gg;
            float x = (even && t <= thr) ? 1.0f : 0.f;
            mrow[t] = make_float4(x, 0.f, 0.f, 0.f);
        }
    }
}

// ---------------------------------------------------------------------------
// PV GEMM, split-bf16 mma, 2-stage cp.async pipeline, k16 chunks.
// A = whi/wlo [i][c] (unnormalized), B = vthi/vtlo [d][c].
// Epilogue divides by g_rowsum. Causal chunk skip, heavy tiles first.
// ---------------------------------------------------------------------------
__global__ __launch_bounds__(256) void pv_mma_kernel(float* __restrict__ out)
{
    const int b  = blockIdx.z;
    const int mt = 31 - blockIdx.y;   // heavy tiles first
    const int nt = blockIdx.x;
    const int i0 = mt * 128;
    const int d0 = nt * 64;

    __shared__ unsigned sA[2][2][128 * PITCH];
    __shared__ unsigned sB[2][2][64 * PITCH];

    const int tid  = threadIdx.x;
    const int lane = tid & 31;
    const int wid  = tid >> 5;
    const int wm   = wid & 3;
    const int wn   = wid >> 2;
    const int g    = lane >> 2;
    const int tq   = lane & 3;

    const unsigned* wh = g_whi + ((long)b * SS + i0) * NKP2;
    const unsigned* wl = g_wlo + ((long)b * SS + i0) * NKP2;
    const unsigned* vh = g_vthi + ((long)b * DD + d0) * NKP2;
    const unsigned* vl = g_vtlo + ((long)b * DD + d0) * NKP2;

    const int lr = tid >> 1;
    const int lc = (tid & 1) * 4;

    float acc[2][4][4];
#pragma unroll
    for (int m = 0; m < 2; m++)
#pragma unroll
        for (int n = 0; n < 4; n++)
#pragma unroll
            for (int e = 0; e < 4; e++) acc[m][n][e] = 0.f;

    int nch = ((128 * mt + 127) >> 7) + 1;   // k16 chunks with any valid key
    if (nch > 32) nch = 32;

#define PV_LOAD(ch, st)                                                          \
    do {                                                                         \
        int kb = (ch) * 8;                                                       \
        cp16(&sA[st][0][lr * PITCH + lc], wh + (long)lr * NKP2 + kb + lc);       \
        cp16(&sA[st][1][lr * PITCH + lc], wl + (long)lr * NKP2 + kb + lc);       \
        if (tid < 128) {                                                         \
            cp16(&sB[st][0][lr * PITCH + lc], vh + (long)lr * NKP2 + kb + lc);   \
            cp16(&sB[st][1][lr * PITCH + lc], vl + (long)lr * NKP2 + kb + lc);   \
        }                                                                        \
    } while (0)

    PV_LOAD(0, 0); CP_COMMIT();

    for (int ch = 0; ch < nch; ch++) {
        const int st = ch & 1;
        if (ch + 1 < nch) { PV_LOAD(ch + 1, st ^ 1); CP_COMMIT(); CP_WAIT1(); }
        else              { CP_WAIT0(); }
        __syncthreads();

        unsigned Ah[2][4], Al[2][4], Bh[4][2], Bl[4][2];
#pragma unroll
        for (int m = 0; m < 2; m++) {
            int r = wm * 32 + m * 16 + g;
            Ah[m][0] = sA[st][0][r * PITCH + tq];
            Ah[m][1] = sA[st][0][(r + 8) * PITCH + tq];
            Ah[m][2] = sA[st][0][r * PITCH + 4 + tq];
            Ah[m][3] = sA[st][0][(r + 8) * PITCH + 4 + tq];
            Al[m][0] = sA[st][1][r * PITCH + tq];
            Al[m][1] = sA[st][1][(r + 8) * PITCH + tq];
            Al[m][2] = sA[st][1][r * PITCH + 4 + tq];
            Al[m][3] = sA[st][1][(r + 8) * PITCH + 4 + tq];
        }
#pragma unroll
        for (int n = 0; n < 4; n++) {
            int c = wn * 32 + n * 8 + g;
            Bh[n][0] = sB[st][0][c * PITCH + tq];
            Bh[n][1] = sB[st][0][c * PITCH + 4 + tq];
            Bl[n][0] = sB[st][1][c * PITCH + tq];
            Bl[n][1] = sB[st][1][c * PITCH + 4 + tq];
        }
#pragma unroll
        for (int m = 0; m < 2; m++)
#pragma unroll
            for (int n = 0; n < 4; n++) {
                mma_bf16(acc[m][n], Ah[m], Bh[n]);
                mma_bf16(acc[m][n], Ah[m], Bl[n]);
                mma_bf16(acc[m][n], Al[m], Bh[n]);
            }
        __syncthreads();
    }
#undef PV_LOAD

    // epilogue: normalize by rowsum, float2 stores
#pragma unroll
    for (int m = 0; m < 2; m++) {
        int ia = i0 + wm * 32 + m * 16 + g;
        float inv0 = 1.0f / g_rowsum[b * SS + ia];
        float inv1 = 1.0f / g_rowsum[b * SS + ia + 8];
#pragma unroll
        for (int n = 0; n < 4; n++) {
            int da = d0 + wn * 32 + n * 8 + 2 * tq;
            *reinterpret_cast<float2*>(out + ((long)b * SS + ia) * DD + da) =
                make_float2(acc[m][n][0] * inv0, acc[m][n][1] * inv0);
            *reinterpret_cast<float2*>(out + ((long)b * SS + ia + 8) * DD + da) =
                make_float2(acc[m][n][2] * inv1, acc[m][n][3] * inv1);
        }
    }
}

// ---------------------------------------------------------------------------
// Launch
// ---------------------------------------------------------------------------
extern "C" void kernel_launch(void* const* d_in, const int* in_sizes, int n_in,
                              void* d_out, int out_size)
{
    const float* q = (const float*)d_in[0];
    const float* k = (const float*)d_in[1];
    const float* v = (const float*)d_in[2];
    float* out = (float*)d_out;

    const long n_out  = (long)BB * SS * DD;       //  8,388,608
    const long n_attn = (long)BB * SS * SS;       // 67,108,864
    const long n_mask = (long)SS * SS;            // 16,777,216
    const long need = n_out + n_attn + n_mask;

    const int full = ((long)out_size >= need) ? 1 : 0;
    float* attn = out + n_out;
    float* mask = attn + n_attn;

    prep_qk_kernel<<<4096, 256>>>(q, k);
    transpose_v_kernel<<<dim3(16, 16, BB), 256>>>(v);

    qk_mma_kernel<<<dim3(NK / 64, SS / 128, BB), 256>>>();

    attn_write_kernel<<<(BB * SS + SS) / 8, 256>>>(attn, mask, full);

    pv_mma_kernel<<<dim3(DD / 64, SS / 128, BB), 256>>>(out);
}

// round 10
// speedup vs baseline: 2.5155x; 1.0592x over previous
#include <cuda_runtime.h>
#include <cuda_bf16.h>

// Problem constants (StridedSparseAttention: B=4, S=4096, D=512, STRIDE=8)
#define BB 4
#define SS 4096
#define DD 512
#define NK 512          // number of strided keys = S/8
#define KSTRIDE 8
#define DP2 256         // DD/2 (b32 pairs per row)
#define NKP2 256        // NK/2
#define PITCH 12        // smem row pitch in uints for 8-uint rows (conflict-free)

#define SCALE 0.044194173824159216f   // 1/sqrt(512)

// Scratch (device globals — no allocations allowed). uint = packed bf16x2.
__device__ unsigned g_qhi[(long)BB * SS * DP2];
__device__ unsigned g_qlo[(long)BB * SS * DP2];
__device__ unsigned g_khi[BB * NK * DP2];
__device__ unsigned g_klo[BB * NK * DP2];
__device__ unsigned g_vthi[BB * DD * NKP2];      // vT[d][c] hi
__device__ unsigned g_vtlo[BB * DD * NKP2];
__device__ unsigned g_whi[(long)BB * SS * NKP2]; // UNnormalized exp(score), bf16 hi
__device__ unsigned g_wlo[(long)BB * SS * NKP2];
// Deterministic rowsum partials: 16 slots per row = [nt(0..7)][wn(0..1)].
// Slot (nt,wn) is written by the qk tile (mt=i>>7, nt) warp wn iff that tile
// is not causally skipped; consumers only read slots of non-skipped tiles.
__device__ float g_rspart[(long)BB * SS * 16];

// ---------------------------------------------------------------------------
// helpers
// ---------------------------------------------------------------------------
__device__ __forceinline__ void split2(float x, float y, unsigned& hi, unsigned& lo) {
    __nv_bfloat16 hx = __float2bfloat16_rn(x);
    __nv_bfloat16 hy = __float2bfloat16_rn(y);
    float rx = x - __bfloat162float(hx);
    float ry = y - __bfloat162float(hy);
    __nv_bfloat162 h2; h2.x = hx; h2.y = hy;
    __nv_bfloat162 l2; l2.x = __float2bfloat16_rn(rx); l2.y = __float2bfloat16_rn(ry);
    hi = *reinterpret_cast<unsigned*>(&h2);
    lo = *reinterpret_cast<unsigned*>(&l2);
}

__device__ __forceinline__ void mma_bf16(float* d, const unsigned* a, const unsigned* b) {
    asm volatile(
        "mma.sync.aligned.m16n8k16.row.col.f32.bf16.bf16.f32 "
        "{%0,%1,%2,%3},{%4,%5,%6,%7},{%8,%9},{%0,%1,%2,%3};\n"
        : "+f"(d[0]), "+f"(d[1]), "+f"(d[2]), "+f"(d[3])
        : "r"(a[0]), "r"(a[1]), "r"(a[2]), "r"(a[3]), "r"(b[0]), "r"(b[1]));
}

__device__ __forceinline__ void cp16(unsigned* smem, const unsigned* gmem) {
    unsigned s = (unsigned)__cvta_generic_to_shared(smem);
    asm volatile("cp.async.cg.shared.global [%0], [%1], 16;\n" :: "r"(s), "l"(gmem));
}
#define CP_COMMIT() asm volatile("cp.async.commit_group;\n")
#define CP_WAIT1()  asm volatile("cp.async.wait_group 1;\n")
#define CP_WAIT0()  asm volatile("cp.async.wait_group 0;\n")

// Deterministic rowsum: fixed-order reduction over the valid partial slots.
// i = row index within the sequence (0..SS-1), row = b*SS + i.
__device__ __forceinline__ float row_sum(long row, int i) {
    const int nv = ((i | 127) >> 9) + 1;         // valid nt tiles for this row
    const float* p = &g_rspart[row * 16];
    float s = 0.f;
    for (int j = 0; j < 2 * nv; j++) s += p[j];
    return s;
}

// ---------------------------------------------------------------------------
// Fused prep (one launch, independent block groups):
//   blocks [0,4096):    q -> hi/lo split; strided k -> khi/klo
//   blocks [4096,5120): strided v -> transposed vT[d][c] hi/lo
//   blocks [5120,5632): mask rows of d_out
// ---------------------------------------------------------------------------
__global__ __launch_bounds__(256) void prep_fused_kernel(
    const float* __restrict__ q, const float* __restrict__ k,
    const float* __restrict__ v, float* __restrict__ mask, int full)
{
    __shared__ float sm[32][33];
    const int bx = blockIdx.x;

    if (bx < 4096) {
        const long NQ  = (long)BB * SS * DP2;
        const long NKU = (long)BB * NK * DP2;
        const long str = 4096L * 256;
        long t0 = (long)bx * 256 + threadIdx.x;

        for (long t = t0; t < NQ; t += str) {
            float2 f = reinterpret_cast<const float2*>(q)[t];
            unsigned hi, lo; split2(f.x, f.y, hi, lo);
            g_qhi[t] = hi; g_qlo[t] = lo;
        }
        for (long t = t0; t < NKU; t += str) {
            int b  = (int)(t / (NK * DP2));
            int r  = (int)((t / DP2) % NK);
            int dq = (int)(t % DP2);
            float2 f = reinterpret_cast<const float2*>(k)[((long)b * SS + KSTRIDE * r) * DP2 + dq];
            unsigned hi, lo; split2(f.x, f.y, hi, lo);
            g_khi[t] = hi; g_klo[t] = lo;
        }
    } else if (bx < 5120) {
        // V transpose: 32x32 tile. decode (b, d-tile, c-tile)
        const int t  = bx - 4096;
        const int b  = t >> 8;
        const int rem = t & 255;
        const int c0 = (rem & 15) * 32;
        const int d0 = (rem >> 4) * 32;
        const int tid = threadIdx.x;
        const int r = tid >> 3;      // 0..31
        const int j = tid & 7;       // 0..7

        float4 f = *reinterpret_cast<const float4*>(
            v + ((long)b * SS + KSTRIDE * (c0 + r)) * DD + d0 + 4 * j);
        sm[r][4 * j + 0] = f.x; sm[r][4 * j + 1] = f.y;
        sm[r][4 * j + 2] = f.z; sm[r][4 * j + 3] = f.w;
        __syncthreads();

        float v0 = sm[4 * j + 0][r], v1 = sm[4 * j + 1][r];
        float v2 = sm[4 * j + 2][r], v3 = sm[4 * j + 3][r];
        unsigned h0, l0, h1, l1;
        split2(v0, v1, h0, l0);
        split2(v2, v3, h1, l1);
        long base = ((long)b * DD + d0 + r) * NKP2 + (c0 >> 1) + 2 * j;
        g_vthi[base] = h0; g_vthi[base + 1] = h1;
        g_vtlo[base] = l0; g_vtlo[base + 1] = l1;
    } else if (full) {
        // mask rows: one warp per row
        const int i    = (bx - 5120) * 8 + (threadIdx.x >> 5);   // 0..S-1
        const int lane = threadIdx.x & 31;
        float4* mrow = reinterpret_cast<float4*>(mask + (long)i * SS);
        const int thr = i >> 2;                  // t <= thr && t even -> 1
        const bool even = (lane & 1) == 0;
#pragma unroll 4
        for (int gg = 0; gg < 32; gg++) {
            int t4 = lane + 32 * gg;
            float x = (even && t4 <= thr) ? 1.0f : 0.f;
            mrow[t4] = make_float4(x, 0.f, 0.f, 0.f);
        }
    }
}

// ---------------------------------------------------------------------------
// QK GEMM, split-bf16 mma, 2-stage cp.async pipeline, k16 chunks.
// CTA 128(i) x 64(c), 8 warps (4M x 2N), warp tile 32x32.
// Epilogue writes UNnormalized whi/wlo (causal-zeroed) AND the deterministic
// rowsum partials g_rspart[row][nt*2+wn].
// ---------------------------------------------------------------------------
__global__ __launch_bounds__(256) void qk_mma_kernel()
{
    const int b  = blockIdx.z;
    const int mt = blockIdx.y;
    const int nt = blockIdx.x;
    const int i0 = mt * 128;
    const int c0 = nt * 64;
    if (8 * c0 > i0 + 127) return;   // fully masked tile

    __shared__ unsigned sA[2][2][128 * PITCH];   // [stage][hi/lo]
    __shared__ unsigned sB[2][2][64 * PITCH];

    const int tid  = threadIdx.x;
    const int lane = tid & 31;
    const int wid  = tid >> 5;
    const int wm   = wid & 3;
    const int wn   = wid >> 2;
    const int g    = lane >> 2;
    const int tq   = lane & 3;

    const unsigned* qh = g_qhi + ((long)b * SS + i0) * DP2;
    const unsigned* ql = g_qlo + ((long)b * SS + i0) * DP2;
    const unsigned* kh = g_khi + ((long)b * NK + c0) * DP2;
    const unsigned* kl = g_klo + ((long)b * NK + c0) * DP2;

    const int lr = tid >> 1;          // 0..127
    const int lc = (tid & 1) * 4;     // 0 or 4

    float acc[2][4][4];
#pragma unroll
    for (int m = 0; m < 2; m++)
#pragma unroll
        for (int n = 0; n < 4; n++)
#pragma unroll
            for (int e = 0; e < 4; e++) acc[m][n][e] = 0.f;

#define QK_LOAD(ch, st)                                                          \
    do {                                                                         \
        int kb = (ch) * 8;                                                       \
        cp16(&sA[st][0][lr * PITCH + lc], qh + (long)lr * DP2 + kb + lc);        \
        cp16(&sA[st][1][lr * PITCH + lc], ql + (long)lr * DP2 + kb + lc);        \
        if (tid < 128) {                                                         \
            cp16(&sB[st][0][lr * PITCH + lc], kh + (long)lr * DP2 + kb + lc);    \
            cp16(&sB[st][1][lr * PITCH + lc], kl + (long)lr * DP2 + kb + lc);    \
        }                                                                        \
    } while (0)

    QK_LOAD(0, 0); CP_COMMIT();

    for (int ch = 0; ch < 32; ch++) {
        const int st = ch & 1;
        if (ch + 1 < 32) { QK_LOAD(ch + 1, st ^ 1); CP_COMMIT(); CP_WAIT1(); }
        else             { CP_WAIT0(); }
        __syncthreads();

        unsigned Ah[2][4], Al[2][4], Bh[4][2], Bl[4][2];
#pragma unroll
        for (int m = 0; m < 2; m++) {
            int r = wm * 32 + m * 16 + g;
            Ah[m][0] = sA[st][0][r * PITCH + tq];
            Ah[m][1] = sA[st][0][(r + 8) * PITCH + tq];
            Ah[m][2] = sA[st][0][r * PITCH + 4 + tq];
            Ah[m][3] = sA[st][0][(r + 8) * PITCH + 4 + tq];
            Al[m][0] = sA[st][1][r * PITCH + tq];
            Al[m][1] = sA[st][1][(r + 8) * PITCH + tq];
            Al[m][2] = sA[st][1][r * PITCH + 4 + tq];
            Al[m][3] = sA[st][1][(r + 8) * PITCH + 4 + tq];
        }
#pragma unroll
        for (int n = 0; n < 4; n++) {
            int c = wn * 32 + n * 8 + g;
            Bh[n][0] = sB[st][0][c * PITCH + tq];
            Bh[n][1] = sB[st][0][c * PITCH + 4 + tq];
            Bl[n][0] = sB[st][1][c * PITCH + tq];
            Bl[n][1] = sB[st][1][c * PITCH + 4 + tq];
        }
#pragma unroll
        for (int m = 0; m < 2; m++)
#pragma unroll
            for (int n = 0; n < 4; n++) {
                mma_bf16(acc[m][n], Ah[m], Bh[n]);
                mma_bf16(acc[m][n], Ah[m], Bl[n]);
                mma_bf16(acc[m][n], Al[m], Bh[n]);
            }
        __syncthreads();
    }
#undef QK_LOAD

    // epilogue: exp + causal predicate -> bf16 hi/lo; rowsum partial per (row,nt,wn)
#pragma unroll
    for (int m = 0; m < 2; m++) {
        int ia = i0 + wm * 32 + m * 16 + g;
        int ib = ia + 8;
        float p0 = 0.f, p1 = 0.f;
#pragma unroll
        for (int n = 0; n < 4; n++) {
            int ca = c0 + wn * 32 + n * 8 + 2 * tq;
            float w0 = (KSTRIDE * ca <= ia)       ? __expf(acc[m][n][0] * SCALE) : 0.f;
            float w1 = (KSTRIDE * (ca + 1) <= ia) ? __expf(acc[m][n][1] * SCALE) : 0.f;
            unsigned hi, lo; split2(w0, w1, hi, lo);
            long u0 = ((long)b * SS + ia) * NKP2 + (ca >> 1);
            g_whi[u0] = hi; g_wlo[u0] = lo;
            float w2 = (KSTRIDE * ca <= ib)       ? __expf(acc[m][n][2] * SCALE) : 0.f;
            float w3 = (KSTRIDE * (ca + 1) <= ib) ? __expf(acc[m][n][3] * SCALE) : 0.f;
            split2(w2, w3, hi, lo);
            long u1 = ((long)b * SS + ib) * NKP2 + (ca >> 1);
            g_whi[u1] = hi; g_wlo[u1] = lo;
            p0 += w0 + w1;
            p1 += w2 + w3;
        }
        // reduce across the 4 tq lanes (same rows), then one lane writes the slot
        p0 += __shfl_xor_sync(0xFFFFFFFFu, p0, 1);
        p0 += __shfl_xor_sync(0xFFFFFFFFu, p0, 2);
        p1 += __shfl_xor_sync(0xFFFFFFFFu, p1, 1);
        p1 += __shfl_xor_sync(0xFFFFFFFFu, p1, 2);
        if (tq == 0) {
            g_rspart[((long)b * SS + ia) * 16 + nt * 2 + wn] = p0;
            g_rspart[((long)b * SS + ib) * 16 + nt * 2 + wn] = p1;
        }
    }
}

// ---------------------------------------------------------------------------
// Fused output kernel:
//   blocks [0,1024):    PV GEMM tiles (cp.async split-bf16 mma, heavy-mt first)
//   blocks [1024,3072): attn rows of d_out (one warp per row)
// Both depend only on qk's whi/wlo + g_rspart -> overlap via co-residency.
// ---------------------------------------------------------------------------
__global__ __launch_bounds__(256) void out_fused_kernel(
    float* __restrict__ out, float* __restrict__ attn, int full)
{
    __shared__ unsigned su[9216];   // 36864 B union: pv(sA 24576 + sB 12288) / attn(16384)

    if (blockIdx.x < 1024) {
        // ------------------ PV branch ------------------
        const int idx = blockIdx.x;
        const int b   = idx >> 8;
        const int rem = idx & 255;
        const int nt  = rem & 7;
        const int mt  = 31 - (rem >> 3);   // heavy tiles first
        const int i0  = mt * 128;
        const int d0  = nt * 64;

#define SA(st, h, i) su[((st) * 2 + (h)) * 1536 + (i)]
#define SB(st, h, i) su[6144 + ((st) * 2 + (h)) * 768 + (i)]

        const int tid  = threadIdx.x;
        const int lane = tid & 31;
        const int wid  = tid >> 5;
        const int wm   = wid & 3;
        const int wn   = wid >> 2;
        const int g    = lane >> 2;
        const int tq   = lane & 3;

        const unsigned* wh = g_whi + ((long)b * SS + i0) * NKP2;
        const unsigned* wl = g_wlo + ((long)b * SS + i0) * NKP2;
        const unsigned* vh = g_vthi + ((long)b * DD + d0) * NKP2;
        const unsigned* vl = g_vtlo + ((long)b * DD + d0) * NKP2;

        const int lr = tid >> 1;
        const int lc = (tid & 1) * 4;

        float acc[2][4][4];
#pragma unroll
        for (int m = 0; m < 2; m++)
#pragma unroll
            for (int n = 0; n < 4; n++)
#pragma unroll
                for (int e = 0; e < 4; e++) acc[m][n][e] = 0.f;

        const int nch = mt + 1;   // k16 chunks with any valid key (<=32)

#define PV_LOAD(ch, st)                                                          \
    do {                                                                         \
        int kb = (ch) * 8;                                                       \
        cp16(&SA(st, 0, lr * PITCH + lc), wh + (long)lr * NKP2 + kb + lc);       \
        cp16(&SA(st, 1, lr * PITCH + lc), wl + (long)lr * NKP2 + kb + lc);       \
        if (tid < 128) {                                                         \
            cp16(&SB(st, 0, lr * PITCH + lc), vh + (long)lr * NKP2 + kb + lc);   \
            cp16(&SB(st, 1, lr * PITCH + lc), vl + (long)lr * NKP2 + kb + lc);   \
        }                                                                        \
    } while (0)

        PV_LOAD(0, 0); CP_COMMIT();

        for (int ch = 0; ch < nch; ch++) {
            const int st = ch & 1;
            if (ch + 1 < nch) { PV_LOAD(ch + 1, st ^ 1); CP_COMMIT(); CP_WAIT1(); }
            else              { CP_WAIT0(); }
            __syncthreads();

            unsigned Ah[2][4], Al[2][4], Bh[4][2], Bl[4][2];
#pragma unroll
            for (int m = 0; m < 2; m++) {
                int r = wm * 32 + m * 16 + g;
                Ah[m][0] = SA(st, 0, r * PITCH + tq);
                Ah[m][1] = SA(st, 0, (r + 8) * PITCH + tq);
                Ah[m][2] = SA(st, 0, r * PITCH + 4 + tq);
                Ah[m][3] = SA(st, 0, (r + 8) * PITCH + 4 + tq);
                Al[m][0] = SA(st, 1, r * PITCH + tq);
                Al[m][1] = SA(st, 1, (r + 8) * PITCH + tq);
                Al[m][2] = SA(st, 1, r * PITCH + 4 + tq);
                Al[m][3] = SA(st, 1, (r + 8) * PITCH + 4 + tq);
            }
#pragma unroll
            for (int n = 0; n < 4; n++) {
                int c = wn * 32 + n * 8 + g;
                Bh[n][0] = SB(st, 0, c * PITCH + tq);
                Bh[n][1] = SB(st, 0, c * PITCH + 4 + tq);
                Bl[n][0] = SB(st, 1, c * PITCH + tq);
                Bl[n][1] = SB(st, 1, c * PITCH + 4 + tq);
            }
#pragma unroll
            for (int m = 0; m < 2; m++)
#pragma unroll
                for (int n = 0; n < 4; n++) {
                    mma_bf16(acc[m][n], Ah[m], Bh[n]);
                    mma_bf16(acc[m][n], Ah[m], Bl[n]);
                    mma_bf16(acc[m][n], Al[m], Bh[n]);
                }
            __syncthreads();
        }
#undef PV_LOAD
#undef SA
#undef SB

        // epilogue: normalize by deterministic rowsum, float2 stores
#pragma unroll
        for (int m = 0; m < 2; m++) {
            int ia = i0 + wm * 32 + m * 16 + g;
            int ib = ia + 8;
            float inv0 = 1.0f / row_sum((long)b * SS + ia, ia);
            float inv1 = 1.0f / row_sum((long)b * SS + ib, ib);
#pragma unroll
            for (int n = 0; n < 4; n++) {
                int da = d0 + wn * 32 + n * 8 + 2 * tq;
                *reinterpret_cast<float2*>(out + ((long)b * SS + ia) * DD + da) =
                    make_float2(acc[m][n][0] * inv0, acc[m][n][1] * inv0);
                *reinterpret_cast<float2*>(out + ((long)b * SS + ib) * DD + da) =
                    make_float2(acc[m][n][2] * inv1, acc[m][n][3] * inv1);
            }
        }
    } else if (full) {
        // ------------------ attn-row branch ------------------
        float* sw = reinterpret_cast<float*>(su);    // [8][512]
        const int wp   = threadIdx.x >> 5;
        const int row  = (blockIdx.x - 1024) * 8 + wp;   // 0 .. B*S-1
        const int lane = threadIdx.x & 31;

        const int i    = row & (SS - 1);
        const int cmax = i >> 3;

#pragma unroll
        for (int qd = 0; qd < 4; qd++) {
            int u = lane + 32 * qd;                  // uint2 index: values 4u..4u+3
            int base = 4 * u;
            uint2 H = *reinterpret_cast<const uint2*>(&g_whi[(long)row * NKP2 + 2 * u]);
            uint2 L = *reinterpret_cast<const uint2*>(&g_wlo[(long)row * NKP2 + 2 * u]);
            float2 h0 = __bfloat1622float2(*reinterpret_cast<__nv_bfloat162*>(&H.x));
            float2 h1 = __bfloat1622float2(*reinterpret_cast<__nv_bfloat162*>(&H.y));
            float2 l0 = __bfloat1622float2(*reinterpret_cast<__nv_bfloat162*>(&L.x));
            float2 l1 = __bfloat1622float2(*reinterpret_cast<__nv_bfloat162*>(&L.y));
            float w0 = (base     <= cmax) ? h0.x + l0.x : 0.f;
            float w1 = (base + 1 <= cmax) ? h0.y + l0.y : 0.f;
            float w2 = (base + 2 <= cmax) ? h1.x + l1.x : 0.f;
            float w3 = (base + 3 <= cmax) ? h1.y + l1.y : 0.f;
            *reinterpret_cast<float4*>(&sw[wp * 512 + base]) = make_float4(w0, w1, w2, w3);
        }
        const float inv = 1.0f / row_sum(row, i);    // c=0 always valid -> s>0
        __syncwarp();

        float4* arow = reinterpret_cast<float4*>(attn + (long)row * SS);
        const int half = lane >> 1;
        const bool even = (lane & 1) == 0;
#pragma unroll 4
        for (int gg = 0; gg < 32; gg++) {
            int t = lane + 32 * gg;                  // float4 index within row
            float x = 0.f;
            if (even) x = sw[wp * 512 + half + 16 * gg] * inv;   // zeros beyond cmax
            arow[t] = make_float4(x, 0.f, 0.f, 0.f);
        }
    }
}

// ---------------------------------------------------------------------------
// Launch: 3 kernels, single stream. Overlap comes from fused independent
// block groups, not from streams (graph-capture-safe).
// ---------------------------------------------------------------------------
extern "C" void kernel_launch(void* const* d_in, const int* in_sizes, int n_in,
                              void* d_out, int out_size)
{
    const float* q = (const float*)d_in[0];
    const float* k = (const float*)d_in[1];
    const float* v = (const float*)d_in[2];
    float* out = (float*)d_out;

    const long n_out  = (long)BB * SS * DD;       //  8,388,608
    const long n_attn = (long)BB * SS * SS;       // 67,108,864
    const long n_mask = (long)SS * SS;            // 16,777,216
    const long need = n_out + n_attn + n_mask;

    const int full = ((long)out_size >= need) ? 1 : 0;
    float* attn = out + n_out;
    float* mask = attn + n_attn;

    // prep: q/k split (4096 blocks) + v transpose (1024) + mask rows (512)
    prep_fused_kernel<<<5632, 256>>>(q, k, v, mask, full);

    // QK GEMM: w (bf16 hi/lo) + deterministic rowsum partials
    qk_mma_kernel<<<dim3(NK / 64, SS / 128, BB), 256>>>();

    // PV GEMM (1024 blocks) + attn rows (2048 blocks), overlapped
    out_fused_kernel<<<3072, 256>>>(out, attn, full);
}

// round 11
// speedup vs baseline: 2.5574x; 1.0167x over previous
#include <cuda_runtime.h>
#include <cuda_bf16.h>

// Problem constants (StridedSparseAttention: B=4, S=4096, D=512, STRIDE=8)
#define BB 4
#define SS 4096
#define DD 512
#define NK 512          // number of strided keys = S/8
#define KSTRIDE 8
#define DP2 256         // DD/2 (b32 pairs per row)
#define NKP2 256        // NK/2
#define PITCH 12        // smem row pitch in uints for 8-uint rows (conflict-free)

#define SCALE 0.044194173824159216f   // 1/sqrt(512)

// Scratch (device globals — no allocations allowed). uint = packed bf16x2.
__device__ unsigned g_qhi[(long)BB * SS * DP2];
__device__ unsigned g_qlo[(long)BB * SS * DP2];
__device__ unsigned g_khi[BB * NK * DP2];
__device__ unsigned g_klo[BB * NK * DP2];
__device__ unsigned g_vthi[BB * DD * NKP2];      // vT[d][c] hi
__device__ unsigned g_vtlo[BB * DD * NKP2];
__device__ unsigned g_whi[(long)BB * SS * NKP2]; // UNnormalized exp(score), bf16 hi
__device__ unsigned g_wlo[(long)BB * SS * NKP2];
// Deterministic rowsum partials: 16 slots per row = [nt(0..7)][wn(0..1)].
__device__ float g_rspart[(long)BB * SS * 16];

// ---------------------------------------------------------------------------
// helpers
// ---------------------------------------------------------------------------
__device__ __forceinline__ void split2(float x, float y, unsigned& hi, unsigned& lo) {
    __nv_bfloat16 hx = __float2bfloat16_rn(x);
    __nv_bfloat16 hy = __float2bfloat16_rn(y);
    float rx = x - __bfloat162float(hx);
    float ry = y - __bfloat162float(hy);
    __nv_bfloat162 h2; h2.x = hx; h2.y = hy;
    __nv_bfloat162 l2; l2.x = __float2bfloat16_rn(rx); l2.y = __float2bfloat16_rn(ry);
    hi = *reinterpret_cast<unsigned*>(&h2);
    lo = *reinterpret_cast<unsigned*>(&l2);
}

__device__ __forceinline__ void mma_bf16(float* d, const unsigned* a, const unsigned* b) {
    asm volatile(
        "mma.sync.aligned.m16n8k16.row.col.f32.bf16.bf16.f32 "
        "{%0,%1,%2,%3},{%4,%5,%6,%7},{%8,%9},{%0,%1,%2,%3};\n"
        : "+f"(d[0]), "+f"(d[1]), "+f"(d[2]), "+f"(d[3])
        : "r"(a[0]), "r"(a[1]), "r"(a[2]), "r"(a[3]), "r"(b[0]), "r"(b[1]));
}

__device__ __forceinline__ void ldsm_x4(unsigned& r0, unsigned& r1,
                                        unsigned& r2, unsigned& r3, unsigned saddr) {
    asm volatile("ldmatrix.sync.aligned.m8n8.x4.shared.b16 {%0,%1,%2,%3}, [%4];"
                 : "=r"(r0), "=r"(r1), "=r"(r2), "=r"(r3) : "r"(saddr));
}

__device__ __forceinline__ void cp16(unsigned* smem, const unsigned* gmem) {
    unsigned s = (unsigned)__cvta_generic_to_shared(smem);
    asm volatile("cp.async.cg.shared.global [%0], [%1], 16;\n" :: "r"(s), "l"(gmem));
}
#define CP_COMMIT() asm volatile("cp.async.commit_group;\n")
#define CP_WAIT1()  asm volatile("cp.async.wait_group 1;\n")
#define CP_WAIT0()  asm volatile("cp.async.wait_group 0;\n")

// Deterministic rowsum: fixed-order reduction over the valid partial slots.
__device__ __forceinline__ float row_sum(long row, int i) {
    const int nv = ((i | 127) >> 9) + 1;         // valid nt tiles for this row
    const float* p = &g_rspart[row * 16];
    float s = 0.f;
    for (int j = 0; j < 2 * nv; j++) s += p[j];
    return s;
}

// ---------------------------------------------------------------------------
// Fused prep (one launch, independent block groups):
//   blocks [0,4096):    q -> hi/lo split; strided k -> khi/klo
//   blocks [4096,5120): strided v -> transposed vT[d][c] hi/lo
//   blocks [5120,5632): mask rows of d_out
// ---------------------------------------------------------------------------
__global__ __launch_bounds__(256) void prep_fused_kernel(
    const float* __restrict__ q, const float* __restrict__ k,
    const float* __restrict__ v, float* __restrict__ mask, int full)
{
    __shared__ float sm[32][33];
    const int bx = blockIdx.x;

    if (bx < 4096) {
        const long NQ  = (long)BB * SS * DP2;
        const long NKU = (long)BB * NK * DP2;
        const long str = 4096L * 256;
        long t0 = (long)bx * 256 + threadIdx.x;

        for (long t = t0; t < NQ; t += str) {
            float2 f = reinterpret_cast<const float2*>(q)[t];
            unsigned hi, lo; split2(f.x, f.y, hi, lo);
            g_qhi[t] = hi; g_qlo[t] = lo;
        }
        for (long t = t0; t < NKU; t += str) {
            int b  = (int)(t / (NK * DP2));
            int r  = (int)((t / DP2) % NK);
            int dq = (int)(t % DP2);
            float2 f = reinterpret_cast<const float2*>(k)[((long)b * SS + KSTRIDE * r) * DP2 + dq];
            unsigned hi, lo; split2(f.x, f.y, hi, lo);
            g_khi[t] = hi; g_klo[t] = lo;
        }
    } else if (bx < 5120) {
        // V transpose: 32x32 tile. decode (b, d-tile, c-tile)
        const int t  = bx - 4096;
        const int b  = t >> 8;
        const int rem = t & 255;
        const int c0 = (rem & 15) * 32;
        const int d0 = (rem >> 4) * 32;
        const int tid = threadIdx.x;
        const int r = tid >> 3;      // 0..31
        const int j = tid & 7;       // 0..7

        float4 f = *reinterpret_cast<const float4*>(
            v + ((long)b * SS + KSTRIDE * (c0 + r)) * DD + d0 + 4 * j);
        sm[r][4 * j + 0] = f.x; sm[r][4 * j + 1] = f.y;
        sm[r][4 * j + 2] = f.z; sm[r][4 * j + 3] = f.w;
        __syncthreads();

        float v0 = sm[4 * j + 0][r], v1 = sm[4 * j + 1][r];
        float v2 = sm[4 * j + 2][r], v3 = sm[4 * j + 3][r];
        unsigned h0, l0, h1, l1;
        split2(v0, v1, h0, l0);
        split2(v2, v3, h1, l1);
        long base = ((long)b * DD + d0 + r) * NKP2 + (c0 >> 1) + 2 * j;
        g_vthi[base] = h0; g_vthi[base + 1] = h1;
        g_vtlo[base] = l0; g_vtlo[base + 1] = l1;
    } else if (full) {
        // mask rows: one warp per row
        const int i    = (bx - 5120) * 8 + (threadIdx.x >> 5);   // 0..S-1
        const int lane = threadIdx.x & 31;
        float4* mrow = reinterpret_cast<float4*>(mask + (long)i * SS);
        const int thr = i >> 2;                  // t <= thr && t even -> 1
        const bool even = (lane & 1) == 0;
#pragma unroll 4
        for (int gg = 0; gg < 32; gg++) {
            int t4 = lane + 32 * gg;
            float x = (even && t4 <= thr) ? 1.0f : 0.f;
            mrow[t4] = make_float4(x, 0.f, 0.f, 0.f);
        }
    }
}

// ---------------------------------------------------------------------------
// QK GEMM, split-bf16 mma, 2-stage cp.async pipeline, k16 chunks, ldmatrix
// fragment loads. CTA 128(i) x 64(c), 8 warps (4M x 2N), warp tile 32x32.
// Epilogue writes UNnormalized whi/wlo (causal-zeroed) + rowsum partials.
// ---------------------------------------------------------------------------
__global__ __launch_bounds__(256) void qk_mma_kernel()
{
    const int b  = blockIdx.z;
    const int mt = blockIdx.y;
    const int nt = blockIdx.x;
    const int i0 = mt * 128;
    const int c0 = nt * 64;
    if (8 * c0 > i0 + 127) return;   // fully masked tile

    __shared__ unsigned sA[2][2][128 * PITCH];   // [stage][hi/lo]
    __shared__ unsigned sB[2][2][64 * PITCH];

    const int tid  = threadIdx.x;
    const int lane = tid & 31;
    const int wid  = tid >> 5;
    const int wm   = wid & 3;
    const int wn   = wid >> 2;
    const int g    = lane >> 2;
    const int tq   = lane & 3;

    const unsigned* qh = g_qhi + ((long)b * SS + i0) * DP2;
    const unsigned* ql = g_qlo + ((long)b * SS + i0) * DP2;
    const unsigned* kh = g_khi + ((long)b * NK + c0) * DP2;
    const unsigned* kl = g_klo + ((long)b * NK + c0) * DP2;

    const int lr = tid >> 1;          // 0..127
    const int lc = (tid & 1) * 4;     // 0 or 4

    // ldmatrix per-thread offset within a tile region (bytes)
    const unsigned lo16  = ((lane & 15) * PITCH + (lane >> 4) * 4) * 4u;
    const unsigned baseA = (unsigned)__cvta_generic_to_shared(&sA[0][0][0]);
    const unsigned baseB = (unsigned)__cvta_generic_to_shared(&sB[0][0][0]);

    float acc[2][4][4];
#pragma unroll
    for (int m = 0; m < 2; m++)
#pragma unroll
        for (int n = 0; n < 4; n++)
#pragma unroll
            for (int e = 0; e < 4; e++) acc[m][n][e] = 0.f;

#define QK_LOAD(ch, st)                                                          \
    do {                                                                         \
        int kb = (ch) * 8;                                                       \
        cp16(&sA[st][0][lr * PITCH + lc], qh + (long)lr * DP2 + kb + lc);        \
        cp16(&sA[st][1][lr * PITCH + lc], ql + (long)lr * DP2 + kb + lc);        \
        if (tid < 128) {                                                         \
            cp16(&sB[st][0][lr * PITCH + lc], kh + (long)lr * DP2 + kb + lc);    \
            cp16(&sB[st][1][lr * PITCH + lc], kl + (long)lr * DP2 + kb + lc);    \
        }                                                                        \
    } while (0)

    QK_LOAD(0, 0); CP_COMMIT();

    for (int ch = 0; ch < 32; ch++) {
        const int st = ch & 1;
        if (ch + 1 < 32) { QK_LOAD(ch + 1, st ^ 1); CP_COMMIT(); CP_WAIT1(); }
        else             { CP_WAIT0(); }
        __syncthreads();

        unsigned Ah[2][4], Al[2][4], Bh[4][2], Bl[4][2];
#pragma unroll
        for (int m = 0; m < 2; m++) {
            unsigned rb = (unsigned)(wm * 32 + m * 16) * (PITCH * 4u);
            ldsm_x4(Ah[m][0], Ah[m][1], Ah[m][2], Ah[m][3],
                    baseA + (st * 2 + 0) * (128 * PITCH * 4u) + rb + lo16);
            ldsm_x4(Al[m][0], Al[m][1], Al[m][2], Al[m][3],
                    baseA + (st * 2 + 1) * (128 * PITCH * 4u) + rb + lo16);
        }
#pragma unroll
        for (int p = 0; p < 2; p++) {
            unsigned rb = (unsigned)(wn * 32 + p * 16) * (PITCH * 4u);
            ldsm_x4(Bh[2 * p][0], Bh[2 * p + 1][0], Bh[2 * p][1], Bh[2 * p + 1][1],
                    baseB + (st * 2 + 0) * (64 * PITCH * 4u) + rb + lo16);
            ldsm_x4(Bl[2 * p][0], Bl[2 * p + 1][0], Bl[2 * p][1], Bl[2 * p + 1][1],
                    baseB + (st * 2 + 1) * (64 * PITCH * 4u) + rb + lo16);
        }
#pragma unroll
        for (int m = 0; m < 2; m++)
#pragma unroll
            for (int n = 0; n < 4; n++) {
                mma_bf16(acc[m][n], Ah[m], Bh[n]);
                mma_bf16(acc[m][n], Ah[m], Bl[n]);
                mma_bf16(acc[m][n], Al[m], Bh[n]);
            }
        __syncthreads();
    }
#undef QK_LOAD

    // epilogue: exp + causal predicate -> bf16 hi/lo; rowsum partial per (row,nt,wn)
#pragma unroll
    for (int m = 0; m < 2; m++) {
        int ia = i0 + wm * 32 + m * 16 + g;
        int ib = ia + 8;
        float p0 = 0.f, p1 = 0.f;
#pragma unroll
        for (int n = 0; n < 4; n++) {
            int ca = c0 + wn * 32 + n * 8 + 2 * tq;
            float w0 = (KSTRIDE * ca <= ia)       ? __expf(acc[m][n][0] * SCALE) : 0.f;
            float w1 = (KSTRIDE * (ca + 1) <= ia) ? __expf(acc[m][n][1] * SCALE) : 0.f;
            unsigned hi, lo; split2(w0, w1, hi, lo);
            long u0 = ((long)b * SS + ia) * NKP2 + (ca >> 1);
            g_whi[u0] = hi; g_wlo[u0] = lo;
            float w2 = (KSTRIDE * ca <= ib)       ? __expf(acc[m][n][2] * SCALE) : 0.f;
            float w3 = (KSTRIDE * (ca + 1) <= ib) ? __expf(acc[m][n][3] * SCALE) : 0.f;
            split2(w2, w3, hi, lo);
            long u1 = ((long)b * SS + ib) * NKP2 + (ca >> 1);
            g_whi[u1] = hi; g_wlo[u1] = lo;
            p0 += w0 + w1;
            p1 += w2 + w3;
        }
        p0 += __shfl_xor_sync(0xFFFFFFFFu, p0, 1);
        p0 += __shfl_xor_sync(0xFFFFFFFFu, p0, 2);
        p1 += __shfl_xor_sync(0xFFFFFFFFu, p1, 1);
        p1 += __shfl_xor_sync(0xFFFFFFFFu, p1, 2);
        if (tq == 0) {
            g_rspart[((long)b * SS + ia) * 16 + nt * 2 + wn] = p0;
            g_rspart[((long)b * SS + ib) * 16 + nt * 2 + wn] = p1;
        }
    }
}

// ---------------------------------------------------------------------------
// Fused output kernel:
//   blocks [0,1024):    PV GEMM tiles (cp.async + ldmatrix, heavy-mt first)
//   blocks [1024,3072): attn rows of d_out (one warp per row)
// ---------------------------------------------------------------------------
__global__ __launch_bounds__(256) void out_fused_kernel(
    float* __restrict__ out, float* __restrict__ attn, int full)
{
    __shared__ unsigned su[9216];   // 36864 B union: pv(sA 24576 + sB 12288) / attn(16384)

    if (blockIdx.x < 1024) {
        // ------------------ PV branch ------------------
        const int idx = blockIdx.x;
        const int b   = idx >> 8;
        const int rem = idx & 255;
        const int nt  = rem & 7;
        const int mt  = 31 - (rem >> 3);   // heavy tiles first
        const int i0  = mt * 128;
        const int d0  = nt * 64;

#define SA(st, h, i) su[((st) * 2 + (h)) * 1536 + (i)]
#define SB(st, h, i) su[6144 + ((st) * 2 + (h)) * 768 + (i)]

        const int tid  = threadIdx.x;
        const int lane = tid & 31;
        const int wid  = tid >> 5;
        const int wm   = wid & 3;
        const int wn   = wid >> 2;
        const int g    = lane >> 2;
        const int tq   = lane & 3;

        const unsigned* wh = g_whi + ((long)b * SS + i0) * NKP2;
        const unsigned* wl = g_wlo + ((long)b * SS + i0) * NKP2;
        const unsigned* vh = g_vthi + ((long)b * DD + d0) * NKP2;
        const unsigned* vl = g_vtlo + ((long)b * DD + d0) * NKP2;

        const int lr = tid >> 1;
        const int lc = (tid & 1) * 4;

        const unsigned lo16   = ((lane & 15) * PITCH + (lane >> 4) * 4) * 4u;
        const unsigned baseSU = (unsigned)__cvta_generic_to_shared(&su[0]);

        float acc[2][4][4];
#pragma unroll
        for (int m = 0; m < 2; m++)
#pragma unroll
            for (int n = 0; n < 4; n++)
#pragma unroll
                for (int e = 0; e < 4; e++) acc[m][n][e] = 0.f;

        const int nch = mt + 1;   // k16 chunks with any valid key (<=32)

#define PV_LOAD(ch, st)                                                          \
    do {                                                                         \
        int kb = (ch) * 8;                                                       \
        cp16(&SA(st, 0, lr * PITCH + lc), wh + (long)lr * NKP2 + kb + lc);       \
        cp16(&SA(st, 1, lr * PITCH + lc), wl + (long)lr * NKP2 + kb + lc);       \
        if (tid < 128) {                                                         \
            cp16(&SB(st, 0, lr * PITCH + lc), vh + (long)lr * NKP2 + kb + lc);   \
            cp16(&SB(st, 1, lr * PITCH + lc), vl + (long)lr * NKP2 + kb + lc);   \
        }                                                                        \
    } while (0)

        PV_LOAD(0, 0); CP_COMMIT();

        for (int ch = 0; ch < nch; ch++) {
            const int st = ch & 1;
            if (ch + 1 < nch) { PV_LOAD(ch + 1, st ^ 1); CP_COMMIT(); CP_WAIT1(); }
            else              { CP_WAIT0(); }
            __syncthreads();

            unsigned Ah[2][4], Al[2][4], Bh[4][2], Bl[4][2];
#pragma unroll
            for (int m = 0; m < 2; m++) {
                unsigned rb = (unsigned)(wm * 32 + m * 16) * (PITCH * 4u);
                ldsm_x4(Ah[m][0], Ah[m][1], Ah[m][2], Ah[m][3],
                        baseSU + (st * 2 + 0) * (1536 * 4u) + rb + lo16);
                ldsm_x4(Al[m][0], Al[m][1], Al[m][2], Al[m][3],
                        baseSU + (st * 2 + 1) * (1536 * 4u) + rb + lo16);
            }
#pragma unroll
            for (int p = 0; p < 2; p++) {
                unsigned rb = (unsigned)(wn * 32 + p * 16) * (PITCH * 4u);
                ldsm_x4(Bh[2 * p][0], Bh[2 * p + 1][0], Bh[2 * p][1], Bh[2 * p + 1][1],
                        baseSU + (6144 * 4u) + (st * 2 + 0) * (768 * 4u) + rb + lo16);
                ldsm_x4(Bl[2 * p][0], Bl[2 * p + 1][0], Bl[2 * p][1], Bl[2 * p + 1][1],
                        baseSU + (6144 * 4u) + (st * 2 + 1) * (768 * 4u) + rb + lo16);
            }
#pragma unroll
            for (int m = 0; m < 2; m++)
#pragma unroll
                for (int n = 0; n < 4; n++) {
                    mma_bf16(acc[m][n], Ah[m], Bh[n]);
                    mma_bf16(acc[m][n], Ah[m], Bl[n]);
                    mma_bf16(acc[m][n], Al[m], Bh[n]);
                }
            __syncthreads();
        }
#undef PV_LOAD
#undef SA
#undef SB

        // epilogue: normalize by deterministic rowsum, float2 stores
#pragma unroll
        for (int m = 0; m < 2; m++) {
            int ia = i0 + wm * 32 + m * 16 + g;
            int ib = ia + 8;
            float inv0 = 1.0f / row_sum((long)b * SS + ia, ia);
            float inv1 = 1.0f / row_sum((long)b * SS + ib, ib);
#pragma unroll
            for (int n = 0; n < 4; n++) {
                int da = d0 + wn * 32 + n * 8 + 2 * tq;
                *reinterpret_cast<float2*>(out + ((long)b * SS + ia) * DD + da) =
                    make_float2(acc[m][n][0] * inv0, acc[m][n][1] * inv0);
                *reinterpret_cast<float2*>(out + ((long)b * SS + ib) * DD + da) =
                    make_float2(acc[m][n][2] * inv1, acc[m][n][3] * inv1);
            }
        }
    } else if (full) {
        // ------------------ attn-row branch ------------------
        float* sw = reinterpret_cast<float*>(su);    // [8][512]
        const int wp   = threadIdx.x >> 5;
        const int row  = (blockIdx.x - 1024) * 8 + wp;   // 0 .. B*S-1
        const int lane = threadIdx.x & 31;

        const int i    = row & (SS - 1);
        const int cmax = i >> 3;

#pragma unroll
        for (int qd = 0; qd < 4; qd++) {
            int u = lane + 32 * qd;                  // uint2 index: values 4u..4u+3
            int base = 4 * u;
            uint2 H = *reinterpret_cast<const uint2*>(&g_whi[(long)row * NKP2 + 2 * u]);
            uint2 L = *reinterpret_cast<const uint2*>(&g_wlo[(long)row * NKP2 + 2 * u]);
            float2 h0 = __bfloat1622float2(*reinterpret_cast<__nv_bfloat162*>(&H.x));
            float2 h1 = __bfloat1622float2(*reinterpret_cast<__nv_bfloat162*>(&H.y));
            float2 l0 = __bfloat1622float2(*reinterpret_cast<__nv_bfloat162*>(&L.x));
            float2 l1 = __bfloat1622float2(*reinterpret_cast<__nv_bfloat162*>(&L.y));
            float w0 = (base     <= cmax) ? h0.x + l0.x : 0.f;
            float w1 = (base + 1 <= cmax) ? h0.y + l0.y : 0.f;
            float w2 = (base + 2 <= cmax) ? h1.x + l1.x : 0.f;
            float w3 = (base + 3 <= cmax) ? h1.y + l1.y : 0.f;
            *reinterpret_cast<float4*>(&sw[wp * 512 + base]) = make_float4(w0, w1, w2, w3);
        }
        const float inv = 1.0f / row_sum(row, i);    // c=0 always valid -> s>0
        __syncwarp();

        float4* arow = reinterpret_cast<float4*>(attn + (long)row * SS);
        const int half = lane >> 1;
        const bool even = (lane & 1) == 0;
#pragma unroll 4
        for (int gg = 0; gg < 32; gg++) {
            int t = lane + 32 * gg;                  // float4 index within row
            float x = 0.f;
            if (even) x = sw[wp * 512 + half + 16 * gg] * inv;   // zeros beyond cmax
            arow[t] = make_float4(x, 0.f, 0.f, 0.f);
        }
    }
}

// ---------------------------------------------------------------------------
// Launch: 3 kernels, single stream (graph-capture-safe).
// ---------------------------------------------------------------------------
extern "C" void kernel_launch(void* const* d_in, const int* in_sizes, int n_in,
                              void* d_out, int out_size)
{
    const float* q = (const float*)d_in[0];
    const float* k = (const float*)d_in[1];
    const float* v = (const float*)d_in[2];
    float* out = (float*)d_out;

    const long n_out  = (long)BB * SS * DD;       //  8,388,608
    const long n_attn = (long)BB * SS * SS;       // 67,108,864
    const long n_mask = (long)SS * SS;            // 16,777,216
    const long need = n_out + n_attn + n_mask;

    const int full = ((long)out_size >= need) ? 1 : 0;
    float* attn = out + n_out;
    float* mask = attn + n_attn;

    // prep: q/k split (4096 blocks) + v transpose (1024) + mask rows (512)
    prep_fused_kernel<<<5632, 256>>>(q, k, v, mask, full);

    // QK GEMM: w (bf16 hi/lo) + deterministic rowsum partials
    qk_mma_kernel<<<dim3(NK / 64, SS / 128, BB), 256>>>();

    // PV GEMM (1024 blocks) + attn rows (2048 blocks), overlapped
    out_fused_kernel<<<3072, 256>>>(out, attn, full);
}